// round 8
// baseline (speedup 1.0000x reference)
#include <cuda_runtime.h>
#include <math.h>

#define BB 4
#define BEAMW 5
#define NSEQ 20
#define TMAXX 16
#define BUFL 17
#define VV 50257
#define DD 768
#define HH 12
#define DHH 64
#define NLL 2
#define SSL 128
#define DFFL 3072
#define TOK_SOS 1
#define TOK_EOS 2
#define NEGINF (-1e20f)

// persistent scratch (no allocs allowed)
__device__ float g_x[NSEQ][DD];
__device__ float g_y[NSEQ][DD];
__device__ float g_attn[NSEQ][DD];
__device__ float g_t1[NSEQ * DFFL];
__device__ float g_logits[NSEQ][VV];
__device__ float g_mx[NSEQ];
__device__ float g_lse[NSEQ];
__device__ float g_cacheK[2][NLL][NSEQ][BUFL][DD];
__device__ float g_cacheV[2][NLL][NSEQ][BUFL][DD];
__device__ float g_crossKV[NLL][BB * SSL][2 * DD];
__device__ int   g_buf[BB][BEAMW][BUFL];
__device__ float g_scores[BB][BEAMW];
__device__ int   g_prevK[BB][BEAMW];

// ---- GEMM: out[N][M] = epi(X[N][K] @ W[M][K]^T + bias) (+ resid). K % 128 == 0. ----
#define KST 128
#define NT 20
__global__ __launch_bounds__(128) void gemm_kernel(
    const float* __restrict__ X, const float* __restrict__ W,
    const float* __restrict__ bias, const float* __restrict__ resid,
    float* __restrict__ out, int Nrows, int M, int K, int epi)
{
    __shared__ float4 xs4[NT][KST / 4];
    __shared__ float  ws[KST][33];
    __shared__ float  red[4][NT][32];
    const int tid = threadIdx.x, lane = tid & 31, warp = tid >> 5;
    const int m0 = blockIdx.x * 32, n0 = blockIdx.y * NT;

    float acc[NT];
#pragma unroll
    for (int i = 0; i < NT; i++) acc[i] = 0.f;

    for (int k0 = 0; k0 < K; k0 += KST) {
        for (int f = tid; f < NT * (KST / 4); f += 128) {
            int r = f >> 5, kq = f & 31;
            float4 v = make_float4(0.f, 0.f, 0.f, 0.f);
            if (n0 + r < Nrows)
                v = *(const float4*)(X + (size_t)(n0 + r) * K + k0 + kq * 4);
            xs4[r][kq] = v;
        }
        for (int f = tid; f < 32 * (KST / 4); f += 128) {
            int m = f >> 5, kq = f & 31;
            float4 v = make_float4(0.f, 0.f, 0.f, 0.f);
            if (m0 + m < M)
                v = *(const float4*)(W + (size_t)(m0 + m) * K + k0 + kq * 4);
            ws[kq * 4 + 0][m] = v.x; ws[kq * 4 + 1][m] = v.y;
            ws[kq * 4 + 2][m] = v.z; ws[kq * 4 + 3][m] = v.w;
        }
        __syncthreads();
#pragma unroll
        for (int kq = 0; kq < 8; kq++) {
            int kk = (warp * 8 + kq) * 4;
            float w0 = ws[kk + 0][lane], w1 = ws[kk + 1][lane];
            float w2 = ws[kk + 2][lane], w3 = ws[kk + 3][lane];
#pragma unroll
            for (int n = 0; n < NT; n++) {
                float4 xv = xs4[n][kk >> 2];
                acc[n] += xv.x * w0 + xv.y * w1 + xv.z * w2 + xv.w * w3;
            }
        }
        __syncthreads();
    }
#pragma unroll
    for (int n = 0; n < NT; n++) red[warp][n][lane] = acc[n];
    __syncthreads();
    int m = m0 + lane;
    if (m < M) {
        float bv = bias ? bias[m] : 0.f;
        for (int q = 0; q < 5; q++) {
            int n = warp * 5 + q;
            if (n0 + n >= Nrows) break;
            float s = red[0][n][lane] + red[1][n][lane] + red[2][n][lane] + red[3][n][lane] + bv;
            if (epi == 1) s = fmaxf(s, 0.f);
            else if (epi == 2) s = tanhf(s);
            if (resid) s += resid[(size_t)(n0 + n) * M + m];
            out[(size_t)(n0 + n) * M + m] = s;
        }
    }
}

// ---- reductions ----
__device__ __forceinline__ float blk_sum(float v, float* sh) {
    int lane = threadIdx.x & 31, w = threadIdx.x >> 5, nw = blockDim.x >> 5;
#pragma unroll
    for (int o = 16; o; o >>= 1) v += __shfl_xor_sync(0xffffffffu, v, o);
    if (lane == 0) sh[w] = v;
    __syncthreads();
    if (w == 0) {
        float r = (lane < nw) ? sh[lane] : 0.f;
#pragma unroll
        for (int o = 16; o; o >>= 1) r += __shfl_xor_sync(0xffffffffu, r, o);
        if (lane == 0) sh[0] = r;
    }
    __syncthreads();
    float r = sh[0];
    __syncthreads();
    return r;
}
__device__ __forceinline__ float blk_max(float v, float* sh) {
    int lane = threadIdx.x & 31, w = threadIdx.x >> 5, nw = blockDim.x >> 5;
#pragma unroll
    for (int o = 16; o; o >>= 1) v = fmaxf(v, __shfl_xor_sync(0xffffffffu, v, o));
    if (lane == 0) sh[w] = v;
    __syncthreads();
    if (w == 0) {
        float r = (lane < nw) ? sh[lane] : -INFINITY;
#pragma unroll
        for (int o = 16; o; o >>= 1) r = fmaxf(r, __shfl_xor_sync(0xffffffffu, r, o));
        if (lane == 0) sh[0] = r;
    }
    __syncthreads();
    float r = sh[0];
    __syncthreads();
    return r;
}

__device__ void ln_row(const float* in, const float* gg, const float* bb2, float* out, float* sh) {
    float ls = 0.f;
    for (int d = threadIdx.x; d < DD; d += blockDim.x) ls += in[d];
    float mean = blk_sum(ls, sh) * (1.0f / DD);
    float lv = 0.f;
    for (int d = threadIdx.x; d < DD; d += blockDim.x) { float t = in[d] - mean; lv += t * t; }
    float var = blk_sum(lv, sh) * (1.0f / DD);
    float rstd = rsqrtf(var + 1e-5f);
    for (int d = threadIdx.x; d < DD; d += blockDim.x)
        out[d] = (in[d] - mean) * rstd * gg[d] + bb2[d];
}

__global__ void ln_kernel(const float* in, const float* gg, const float* bb2, float* out) {
    __shared__ float sh[8];
    int n = blockIdx.x;
    ln_row(in + (size_t)n * DD, gg, bb2, out + (size_t)n * DD, sh);
}

__global__ void embed_ln_kernel(const float* __restrict__ emb, const float* __restrict__ pos,
                                const float* gg, const float* bb2, int t) {
    __shared__ float xr[DD];
    __shared__ float sh[8];
    int n = blockIdx.x;
    int tok = g_buf[n / BEAMW][n % BEAMW][t];
    for (int d = threadIdx.x; d < DD; d += blockDim.x)
        xr[d] = emb[(size_t)tok * DD + d] + pos[(size_t)t * DD + d];
    __syncthreads();
    ln_row(xr, gg, bb2, &g_x[n][0], sh);
}

__global__ void copykv_kernel(int l, int t, int pp) {
    int n = blockIdx.x;
    for (int d = threadIdx.x; d < DD; d += blockDim.x) {
        g_cacheK[pp][l][n][t][d] = g_t1[n * (3 * DD) + DD + d];
        g_cacheV[pp][l][n][t][d] = g_t1[n * (3 * DD) + 2 * DD + d];
    }
}

__global__ void selfattn_kernel(int l, int t, int pp) {
    int n = blockIdx.x, h = blockIdx.y, lane = threadIdx.x;
    __shared__ float a[BUFL];
    const float* q = g_t1 + n * (3 * DD) + h * DHH;
    float s = -INFINITY;
    if (lane <= t) {
        const float* Kr = &g_cacheK[pp][l][n][lane][h * DHH];
        float d = 0.f;
#pragma unroll
        for (int i = 0; i < DHH; i++) d += q[i] * Kr[i];
        s = d * 0.125f;
    }
    float mx = s;
#pragma unroll
    for (int o = 16; o; o >>= 1) mx = fmaxf(mx, __shfl_xor_sync(0xffffffffu, mx, o));
    float e = (lane <= t) ? expf(s - mx) : 0.f;
    float sum = e;
#pragma unroll
    for (int o = 16; o; o >>= 1) sum += __shfl_xor_sync(0xffffffffu, sum, o);
    if (lane <= t) a[lane] = e / sum;
    __syncwarp();
    float o0 = 0.f, o1 = 0.f;
    for (int j = 0; j <= t; j++) {
        const float* Vr = &g_cacheV[pp][l][n][j][h * DHH];
        float p = a[j];
        o0 += p * Vr[lane];
        o1 += p * Vr[lane + 32];
    }
    g_attn[n][h * DHH + lane] = o0;
    g_attn[n][h * DHH + lane + 32] = o1;
}

__global__ __launch_bounds__(128) void crossattn_kernel(int l, const int* __restrict__ source_mask) {
    int n = blockIdx.x, h = blockIdx.y, b = n / BEAMW, j = threadIdx.x;
    __shared__ float red[SSL];
    __shared__ float a[SSL];
    const float* q = g_t1 + n * DD + h * DHH;
    const float* Kr = &g_crossKV[l][b * SSL + j][h * DHH];
    float d = 0.f;
#pragma unroll
    for (int i = 0; i < DHH; i++) d += q[i] * Kr[i];
    float s = d * 0.125f;
    if (source_mask[b * SSL + j] == 0) s = -1e9f;
    red[j] = s; __syncthreads();
    for (int st = 64; st >= 1; st >>= 1) { if (j < st) red[j] = fmaxf(red[j], red[j + st]); __syncthreads(); }
    float mx = red[0]; __syncthreads();
    float p = expf(s - mx);
    red[j] = p; __syncthreads();
    for (int st = 64; st >= 1; st >>= 1) { if (j < st) red[j] += red[j + st]; __syncthreads(); }
    float sum = red[0]; __syncthreads();
    a[j] = p / sum; __syncthreads();
    if (j < DHH) {
        float o = 0.f;
        for (int k = 0; k < SSL; k++)
            o += a[k] * g_crossKV[l][b * SSL + k][DD + h * DHH + j];
        g_attn[n][h * DHH + j] = o;
    }
}

__global__ void lse_kernel() {
    __shared__ float sh[8];
    int n = blockIdx.x;
    const float* row = &g_logits[n][0];
    float lm = -INFINITY;
    for (int i = threadIdx.x; i < VV; i += blockDim.x) lm = fmaxf(lm, row[i]);
    float mx = blk_max(lm, sh);
    float ls = 0.f;
    for (int i = threadIdx.x; i < VV; i += blockDim.x) ls += expf(row[i] - mx);
    float s = blk_sum(ls, sh);
    if (threadIdx.x == 0) { g_mx[n] = mx; g_lse[n] = logf(s); }
}

// exact jax.lax.top_k semantics: value desc, ties -> smaller index
__global__ __launch_bounds__(256) void topk_kernel(int t) {
    __shared__ int   s_oldbuf[BEAMW * BUFL];
    __shared__ float s_sc[BEAMW];
    __shared__ int   s_eos[BEAMW];
    __shared__ float mv[256][5];
    __shared__ int   mi[256][5];
    int b = blockIdx.x, tid = threadIdx.x;
    if (tid < BEAMW * BUFL) s_oldbuf[tid] = g_buf[b][tid / BUFL][tid % BUFL];
    if (tid < BEAMW) { s_sc[tid] = g_scores[b][tid]; s_eos[tid] = (g_buf[b][tid][t] == TOK_EOS) ? 1 : 0; }
    __syncthreads();
    float tv[5]; int ti[5];
#pragma unroll
    for (int q = 0; q < 5; q++) { tv[q] = -INFINITY; ti[q] = 0x7fffffff; }
    for (int i = tid; i < BEAMW * VV; i += 256) {
        int j = i / VV, v = i - j * VV;
        float val;
        if (s_eos[j]) val = NEGINF;
        else {
            int nn = b * BEAMW + j;
            val = s_sc[j] + (g_logits[nn][v] - g_mx[nn] - g_lse[nn]);
        }
        if (val > tv[4] || (val == tv[4] && i < ti[4])) {
            int p = 4;
            while (p > 0 && (val > tv[p - 1] || (val == tv[p - 1] && i < ti[p - 1]))) {
                tv[p] = tv[p - 1]; ti[p] = ti[p - 1]; p--;
            }
            tv[p] = val; ti[p] = i;
        }
    }
#pragma unroll
    for (int q = 0; q < 5; q++) { mv[tid][q] = tv[q]; mi[tid][q] = ti[q]; }
    __syncthreads();
    for (int stride = 128; stride >= 1; stride >>= 1) {
        if (tid < stride) {
            float av[5], bv5[5]; int ai[5], bi5[5];
#pragma unroll
            for (int q = 0; q < 5; q++) {
                av[q] = mv[tid][q]; ai[q] = mi[tid][q];
                bv5[q] = mv[tid + stride][q]; bi5[q] = mi[tid + stride][q];
            }
            int ia = 0, ib = 0;
            float rv[5]; int ri[5];
#pragma unroll
            for (int q = 0; q < 5; q++) {
                bool ta = (av[ia] > bv5[ib]) || (av[ia] == bv5[ib] && ai[ia] < bi5[ib]);
                if (ta) { rv[q] = av[ia]; ri[q] = ai[ia]; ia++; }
                else    { rv[q] = bv5[ib]; ri[q] = bi5[ib]; ib++; }
            }
#pragma unroll
            for (int q = 0; q < 5; q++) { mv[tid][q] = rv[q]; mi[tid][q] = ri[q]; }
        }
        __syncthreads();
    }
    if (tid < BEAMW) {
        int id = mi[0][tid];
        int pk = id / VV;
        int tok = id - pk * VV;
        g_scores[b][tid] = mv[0][tid];
        g_prevK[b][tid] = pk;
        for (int p = 0; p < BUFL; p++)
            g_buf[b][tid][p] = (p == t + 1) ? tok : s_oldbuf[pk * BUFL + p];
    }
}

__global__ void gather_kernel(int pp) {
    int j = blockIdx.x, n = blockIdx.y, z = blockIdx.z;
    int l = z >> 1, kv = z & 1;
    int b = n / BEAMW, k = n % BEAMW;
    int src = b * BEAMW + g_prevK[b][k];
    const float* s; float* dpt;
    if (kv == 0) { s = &g_cacheK[pp][l][src][j][0]; dpt = &g_cacheK[1 - pp][l][n][j][0]; }
    else         { s = &g_cacheV[pp][l][src][j][0]; dpt = &g_cacheV[1 - pp][l][n][j][0]; }
    for (int i = threadIdx.x; i < DD; i += blockDim.x) dpt[i] = s[i];
}

__global__ void init_kernel() {
    int tid = threadIdx.x;
    if (tid < BB * BEAMW * BUFL) {
        int b = tid / (BEAMW * BUFL), r = tid % (BEAMW * BUFL);
        int k = r / BUFL, p = r % BUFL;
        g_buf[b][k][p] = (k == 0 && p == 0) ? TOK_SOS : 0;
    }
    if (tid < BB * BEAMW)
        ((float*)g_scores)[tid] = (tid % BEAMW == 0) ? 0.f : NEGINF;
}

__global__ void writeout_kernel(float* out) {
    int tid = threadIdx.x;
    if (tid < BB * BEAMW) {
        int b = tid / BEAMW, k = tid % BEAMW;
        out[tid] = g_scores[b][k];
        int cum = 0;
        for (int i = 1; i <= TMAXX; i++) {
            int tok = g_buf[b][k][i];
            if (tok == TOK_EOS) cum++;
            out[BB * BEAMW + tid * TMAXX + (i - 1)] = (cum == 0) ? (float)tok : 0.f;
        }
    }
}

extern "C" void kernel_launch(void* const* d_in, const int* in_sizes, int n_in,
                              void* d_out, int out_size) {
    (void)in_sizes; (void)n_in; (void)out_size;
    const float* emb         = (const float*)d_in[0];
    const float* pos         = (const float*)d_in[1];
    const float* ln_emb_g    = (const float*)d_in[2];
    const float* ln_emb_b    = (const float*)d_in[3];
    const float* self_in_w   = (const float*)d_in[4];
    const float* self_in_b   = (const float*)d_in[5];
    const float* self_out_w  = (const float*)d_in[6];
    const float* self_out_b  = (const float*)d_in[7];
    const float* cross_in_w  = (const float*)d_in[8];
    const float* cross_in_b  = (const float*)d_in[9];
    const float* cross_out_w = (const float*)d_in[10];
    const float* cross_out_b = (const float*)d_in[11];
    const float* ff1_w       = (const float*)d_in[12];
    const float* ff1_b       = (const float*)d_in[13];
    const float* ff2_w       = (const float*)d_in[14];
    const float* ff2_b       = (const float*)d_in[15];
    const float* ln1_g       = (const float*)d_in[16];
    const float* ln1_b       = (const float*)d_in[17];
    const float* ln2_g       = (const float*)d_in[18];
    const float* ln2_b       = (const float*)d_in[19];
    const float* ln3_g       = (const float*)d_in[20];
    const float* ln3_b       = (const float*)d_in[21];
    const float* dense_w     = (const float*)d_in[22];
    const float* dense_b     = (const float*)d_in[23];
    const float* context     = (const float*)d_in[24];
    const int*   source_mask = (const int*)d_in[25];

    void* tmp;
    float *pt1, *pattn, *px, *py, *plog, *pcross;
    cudaGetSymbolAddress(&tmp, g_t1);      pt1    = (float*)tmp;
    cudaGetSymbolAddress(&tmp, g_attn);    pattn  = (float*)tmp;
    cudaGetSymbolAddress(&tmp, g_x);       px     = (float*)tmp;
    cudaGetSymbolAddress(&tmp, g_y);       py     = (float*)tmp;
    cudaGetSymbolAddress(&tmp, g_logits);  plog   = (float*)tmp;
    cudaGetSymbolAddress(&tmp, g_crossKV); pcross = (float*)tmp;

    init_kernel<<<1, 512>>>();

    // cross-attn K|V precompute: rows D..3D of cross_in_w are contiguous -> one GEMM, M=2*DD
    for (int l = 0; l < NLL; l++) {
        gemm_kernel<<<dim3((2 * DD) / 32, (BB * SSL + NT - 1) / NT), 128>>>(
            context,
            cross_in_w + (size_t)l * 3 * DD * DD + (size_t)DD * DD,
            cross_in_b + (size_t)l * 3 * DD + DD,
            nullptr,
            pcross + (size_t)l * BB * SSL * 2 * DD,
            BB * SSL, 2 * DD, DD, 0);
    }

    int pp = 0;
    for (int t = 0; t < TMAXX; t++) {
        embed_ln_kernel<<<NSEQ, 256>>>(emb, pos, ln_emb_g, ln_emb_b, t);
        for (int l = 0; l < NLL; l++) {
            gemm_kernel<<<dim3(72, 1), 128>>>(px, self_in_w + (size_t)l * 3 * DD * DD,
                self_in_b + (size_t)l * 3 * DD, nullptr, pt1, NSEQ, 3 * DD, DD, 0);
            copykv_kernel<<<NSEQ, 256>>>(l, t, pp);
            selfattn_kernel<<<dim3(NSEQ, HH), 32>>>(l, t, pp);
            gemm_kernel<<<dim3(24, 1), 128>>>(pattn, self_out_w + (size_t)l * DD * DD,
                self_out_b + (size_t)l * DD, px, py, NSEQ, DD, DD, 0);
            ln_kernel<<<NSEQ, 256>>>(py, ln1_g + (size_t)l * DD, ln1_b + (size_t)l * DD, px);

            gemm_kernel<<<dim3(24, 1), 128>>>(px, cross_in_w + (size_t)l * 3 * DD * DD,
                cross_in_b + (size_t)l * 3 * DD, nullptr, pt1, NSEQ, DD, DD, 0);
            crossattn_kernel<<<dim3(NSEQ, HH), 128>>>(l, source_mask);
            gemm_kernel<<<dim3(24, 1), 128>>>(pattn, cross_out_w + (size_t)l * DD * DD,
                cross_out_b + (size_t)l * DD, px, py, NSEQ, DD, DD, 0);
            ln_kernel<<<NSEQ, 256>>>(py, ln2_g + (size_t)l * DD, ln2_b + (size_t)l * DD, px);

            gemm_kernel<<<dim3(96, 1), 128>>>(px, ff1_w + (size_t)l * DFFL * DD,
                ff1_b + (size_t)l * DFFL, nullptr, pt1, NSEQ, DFFL, DD, 1);
            gemm_kernel<<<dim3(24, 1), 128>>>(pt1, ff2_w + (size_t)l * DD * DFFL,
                ff2_b + (size_t)l * DD, px, py, NSEQ, DD, DFFL, 0);
            ln_kernel<<<NSEQ, 256>>>(py, ln3_g + (size_t)l * DD, ln3_b + (size_t)l * DD, px);
        }
        gemm_kernel<<<dim3(24, 1), 128>>>(px, dense_w, dense_b, nullptr, py, NSEQ, DD, DD, 2);
        gemm_kernel<<<dim3((VV + 31) / 32, 1), 128>>>(py, emb, nullptr, nullptr, plog, NSEQ, VV, DD, 0);
        lse_kernel<<<NSEQ, 256>>>();
        topk_kernel<<<BB, 256>>>(t);
        gather_kernel<<<dim3(BUFL, NSEQ, NLL * 2), 192>>>(pp);
        pp ^= 1;
    }
    writeout_kernel<<<1, 64>>>((float*)d_out);
}

// round 12
// speedup vs baseline: 1.4045x; 1.4045x over previous
#include <cuda_runtime.h>
#include <math.h>

#define BB 4
#define BEAMW 5
#define NSEQ 20
#define TMAXX 16
#define BUFL 17
#define VV 50257
#define DD 768
#define HH 12
#define DHH 64
#define NLL 2
#define SSL 128
#define DFFL 3072
#define TOK_SOS 1
#define TOK_EOS 2
#define NEGINF (-1e20f)
#define NBLK 148
#define NTHR 256
#define NWARPT (NBLK * 8)

__device__ float g_x[NSEQ][DD];
__device__ float g_y[NSEQ][DD];
__device__ float g_attn[NSEQ][DD];
__device__ float g_t1[NSEQ * DFFL];
__device__ float g_logits[NSEQ][VV];
__device__ float g_mx[NSEQ];
__device__ float g_lse[NSEQ];
__device__ float g_cacheK[2][NLL][NSEQ][BUFL][DD];
__device__ float g_cacheV[2][NLL][NSEQ][BUFL][DD];
__device__ float g_crossKV[NLL][BB * SSL][2 * DD];
__device__ int   g_buf[BB][BEAMW][BUFL];
__device__ float g_scores[BB][BEAMW];
__device__ int   g_prevK[BB][BEAMW];
__device__ float g_pv[NBLK * 5];
__device__ int   g_pi[NBLK * 5];
__device__ unsigned g_cnt;
__device__ unsigned g_gen;

__device__ __forceinline__ void gsync() {
    __syncthreads();
    __threadfence();
    if (threadIdx.x == 0) {
        unsigned gen = *((volatile unsigned*)&g_gen);
        if (atomicAdd(&g_cnt, 1u) == NBLK - 1u) {
            atomicExch(&g_cnt, 0u);
            __threadfence();
            atomicAdd(&g_gen, 1u);
        } else {
            while (*((volatile unsigned*)&g_gen) == gen) __nanosleep(64);
        }
    }
    __syncthreads();
    __threadfence();
}

__device__ __forceinline__ float wsum(float a) {
#pragma unroll
    for (int o = 16; o; o >>= 1) a += __shfl_xor_sync(0xffffffffu, a, o);
    return a;
}
__device__ __forceinline__ float wmax(float a) {
#pragma unroll
    for (int o = 16; o; o >>= 1) a = fmaxf(a, __shfl_xor_sync(0xffffffffu, a, o));
    return a;
}
__device__ __forceinline__ float dot24(const float4* __restrict__ xr, int lane,
    float4 w0, float4 w1, float4 w2, float4 w3, float4 w4, float4 w5)
{
    float4 x0 = xr[lane], x1 = xr[lane + 32], x2 = xr[lane + 64];
    float4 x3 = xr[lane + 96], x4 = xr[lane + 128], x5 = xr[lane + 160];
    float a = x0.x * w0.x + x0.y * w0.y + x0.z * w0.z + x0.w * w0.w;
    a += x1.x * w1.x + x1.y * w1.y + x1.z * w1.z + x1.w * w1.w;
    a += x2.x * w2.x + x2.y * w2.y + x2.z * w2.z + x2.w * w2.w;
    a += x3.x * w3.x + x3.y * w3.y + x3.z * w3.z + x3.w * w3.w;
    a += x4.x * w4.x + x4.y * w4.y + x4.z * w4.z + x4.w * w4.w;
    a += x5.x * w5.x + x5.y * w5.y + x5.z * w5.z + x5.w * w5.w;
    return a;
}
__device__ __forceinline__ void stage20(const float* __restrict__ X, float* xs) {
    const float4* s = (const float4*)X;
    float4* d = (float4*)xs;
    for (int i = threadIdx.x; i < NSEQ * 192; i += NTHR) d[i] = s[i];
    __syncthreads();
}

// out[20][M] = epi(xs[20][768] @ W[M][768]^T + bias)(+resid); epi 3 = qkv routing
__device__ void gemmA(const float* __restrict__ W, const float* __restrict__ bias,
    const float* __restrict__ resid, float* __restrict__ out, int M, int epi,
    const float* xs, int gw, int lane, int l, int t, int pp)
{
    for (int m = gw; m < M; m += NWARPT) {
        const float4* Wr = (const float4*)(W + (size_t)m * DD);
        float4 w0 = Wr[lane], w1 = Wr[lane + 32], w2 = Wr[lane + 64];
        float4 w3 = Wr[lane + 96], w4 = Wr[lane + 128], w5 = Wr[lane + 160];
        float bv = bias ? bias[m] : 0.f;
        float acc[NSEQ];
#pragma unroll
        for (int n = 0; n < NSEQ; n++)
            acc[n] = wsum(dot24((const float4*)xs + n * 192, lane, w0, w1, w2, w3, w4, w5));
#pragma unroll
        for (int n = 0; n < NSEQ; n++) if (lane == n) {
            float s = acc[n] + bv;
            if (epi == 1) s = fmaxf(s, 0.f);
            else if (epi == 2) s = tanhf(s);
            if (resid) s += resid[n * DD + m];
            if (epi == 3) {
                if (m < DD)          g_t1[n * DD + m] = s;
                else if (m < 2 * DD) g_cacheK[pp][l][n][t][m - DD] = s;
                else                 g_cacheV[pp][l][n][t][m - 2 * DD] = s;
            } else out[(size_t)n * M + m] = s;
        }
    }
}

__device__ void gemm_ff2(const float* __restrict__ W, const float* __restrict__ bias,
    const float* __restrict__ resid, float* __restrict__ out, float* xs,
    int gw, int lane, int tid)
{
    int m = gw;
    bool act = (m < DD);
    float acc[NSEQ];
#pragma unroll
    for (int n = 0; n < NSEQ; n++) acc[n] = 0.f;
    const float4* Wr = (const float4*)(W + (act ? (size_t)m * DFFL : 0));
    for (int c = 0; c < 4; c++) {
        __syncthreads();
        for (int i = tid; i < NSEQ * 192; i += NTHR) {
            int n = i / 192, k = i - n * 192;
            ((float4*)xs)[i] = ((const float4*)(g_t1 + n * DFFL + c * DD))[k];
        }
        __syncthreads();
        if (act) {
            float4 w0 = Wr[c * 192 + lane], w1 = Wr[c * 192 + lane + 32], w2 = Wr[c * 192 + lane + 64];
            float4 w3 = Wr[c * 192 + lane + 96], w4 = Wr[c * 192 + lane + 128], w5 = Wr[c * 192 + lane + 160];
#pragma unroll
            for (int n = 0; n < NSEQ; n++)
                acc[n] += dot24((const float4*)xs + n * 192, lane, w0, w1, w2, w3, w4, w5);
        }
    }
    if (act) {
#pragma unroll
        for (int n = 0; n < NSEQ; n++) {
            float a = wsum(acc[n]);
            if (lane == n) out[n * DD + m] = a + bias[m] + resid[n * DD + m];
        }
    }
}

__device__ __forceinline__ void ln_warp(const float* __restrict__ y, const float* __restrict__ gg,
    const float* __restrict__ bb2, float* __restrict__ xo, int lane)
{
    float v[24]; float s = 0.f;
#pragma unroll
    for (int j = 0; j < 24; j++) { v[j] = y[lane + 32 * j]; s += v[j]; }
    float mean = wsum(s) * (1.f / DD);
    float q = 0.f;
#pragma unroll
    for (int j = 0; j < 24; j++) { float d = v[j] - mean; q += d * d; }
    float rstd = rsqrtf(wsum(q) * (1.f / DD) + 1e-5f);
#pragma unroll
    for (int j = 0; j < 24; j++) {
        int k = lane + 32 * j;
        xo[k] = (v[j] - mean) * rstd * gg[k] + bb2[k];
    }
}

__device__ __forceinline__ void ins5(float v, int id, float* tv, int* ti) {
    if (v > tv[4] || (v == tv[4] && id < ti[4])) {
        int p = 4;
        while (p > 0 && (v > tv[p - 1] || (v == tv[p - 1] && id < ti[p - 1]))) {
            tv[p] = tv[p - 1]; ti[p] = ti[p - 1]; p--;
        }
        tv[p] = v; ti[p] = id;
    }
}

__global__ void __launch_bounds__(NTHR, 1) decode_all(
    const float* __restrict__ emb, const float* __restrict__ pos,
    const float* __restrict__ ln_emb_g, const float* __restrict__ ln_emb_b,
    const float* __restrict__ self_in_w, const float* __restrict__ self_in_b,
    const float* __restrict__ self_out_w, const float* __restrict__ self_out_b,
    const float* __restrict__ cross_in_w, const float* __restrict__ cross_in_b,
    const float* __restrict__ cross_out_w, const float* __restrict__ cross_out_b,
    const float* __restrict__ ff1_w, const float* __restrict__ ff1_b,
    const float* __restrict__ ff2_w, const float* __restrict__ ff2_b,
    const float* __restrict__ ln1_g, const float* __restrict__ ln1_b,
    const float* __restrict__ ln2_g, const float* __restrict__ ln2_b,
    const float* __restrict__ ln3_g, const float* __restrict__ ln3_b,
    const float* __restrict__ dense_w, const float* __restrict__ dense_b,
    const float* __restrict__ context, const int* __restrict__ source_mask,
    float* __restrict__ outbuf)
{
    extern __shared__ float xs[];
    __shared__ float s_red[32];
    const int tid = threadIdx.x, lane = tid & 31, wid = tid >> 5, bid = blockIdx.x;
    const int gw = bid * 8 + wid;

    if (bid == 0) {
        if (tid < BB * BEAMW * BUFL) {
            int b = tid / (BEAMW * BUFL), r = tid % (BEAMW * BUFL), k = r / BUFL, p = r % BUFL;
            g_buf[b][k][p] = (k == 0 && p == 0) ? TOK_SOS : 0;
        }
        if (tid < BB * BEAMW) ((float*)g_scores)[tid] = (tid % BEAMW == 0) ? 0.f : NEGINF;
    }

    // crossKV precompute
    for (int task = bid; task < 2 * 96; task += NBLK) {
        int l = task / 96, mt = task % 96;
        for (int nt = 0; nt < 26; nt++) {
            int base = nt * 20;
            int nr = min(20, BB * SSL - base);
            __syncthreads();
            {
                const float4* s = (const float4*)(context + (size_t)base * DD);
                for (int i = tid; i < nr * 192; i += NTHR) ((float4*)xs)[i] = s[i];
            }
            __syncthreads();
#pragma unroll
            for (int c = 0; c < 2; c++) {
                int m = mt * 16 + wid * 2 + c;
                const float4* Wr = (const float4*)(cross_in_w + (size_t)l * 3 * DD * DD + (size_t)(DD + m) * DD);
                float4 w0 = Wr[lane], w1 = Wr[lane + 32], w2 = Wr[lane + 64];
                float4 w3 = Wr[lane + 96], w4 = Wr[lane + 128], w5 = Wr[lane + 160];
                float bv = cross_in_b[l * 3 * DD + DD + m];
#pragma unroll
                for (int n = 0; n < 20; n++) {
                    float a = wsum(dot24((const float4*)xs + n * 192, lane, w0, w1, w2, w3, w4, w5));
                    if (n < nr && lane == n) g_crossKV[l][base + n][m] = a + bv;
                }
            }
        }
    }
    gsync();

    int pp = 0;
    for (int t = 0; t < TMAXX; t++) {
        if (gw < NSEQ) {
            int n = gw;
            int tok = g_buf[n / BEAMW][n % BEAMW][t];
            float v[24]; float s = 0.f;
#pragma unroll
            for (int j = 0; j < 24; j++) {
                int k = lane + 32 * j;
                v[j] = emb[(size_t)tok * DD + k] + pos[(size_t)t * DD + k];
                s += v[j];
            }
            float mean = wsum(s) * (1.f / DD);
            float q = 0.f;
#pragma unroll
            for (int j = 0; j < 24; j++) { float d = v[j] - mean; q += d * d; }
            float rstd = rsqrtf(wsum(q) * (1.f / DD) + 1e-5f);
#pragma unroll
            for (int j = 0; j < 24; j++) {
                int k = lane + 32 * j;
                g_x[n][k] = (v[j] - mean) * rstd * ln_emb_g[k] + ln_emb_b[k];
            }
        }
        gsync();

        for (int l = 0; l < NLL; l++) {
            stage20(&g_x[0][0], xs);
            gemmA(self_in_w + (size_t)l * 3 * DD * DD, self_in_b + l * 3 * DD,
                  nullptr, nullptr, 3 * DD, 3, xs, gw, lane, l, t, pp);
            gsync();

            if (gw < NSEQ * HH) {
                int n = gw / HH, h = gw % HH;
                const float4* q4 = (const float4*)(g_t1 + n * DD + h * DHH);
                bool actj = (lane <= t);
                float dq = 0.f;
                if (actj) {
                    const float4* k4 = (const float4*)(&g_cacheK[pp][l][n][lane][h * DHH]);
#pragma unroll
                    for (int i = 0; i < 16; i++) {
                        float4 a = q4[i], b = k4[i];
                        dq += a.x * b.x + a.y * b.y + a.z * b.z + a.w * b.w;
                    }
                }
                float sc = actj ? dq * 0.125f : -INFINITY;
                float mx = wmax(sc);
                float e = actj ? expf(sc - mx) : 0.f;
                float aw = e / wsum(e);
                float o0 = 0.f, o1 = 0.f;
                for (int j = 0; j <= t; j++) {
                    float aj = __shfl_sync(0xffffffffu, aw, j);
                    const float* Vr = &g_cacheV[pp][l][n][j][h * DHH];
                    o0 += aj * Vr[lane]; o1 += aj * Vr[lane + 32];
                }
                g_attn[n][h * DHH + lane] = o0;
                g_attn[n][h * DHH + lane + 32] = o1;
            }
            gsync();

            stage20(&g_attn[0][0], xs);
            gemmA(self_out_w + (size_t)l * DD * DD, self_out_b + l * DD,
                  &g_x[0][0], &g_y[0][0], DD, 0, xs, gw, lane, 0, 0, 0);
            gsync();
            if (gw < NSEQ) ln_warp(&g_y[gw][0], ln1_g + l * DD, ln1_b + l * DD, &g_x[gw][0], lane);
            gsync();

            stage20(&g_x[0][0], xs);
            gemmA(cross_in_w + (size_t)l * 3 * DD * DD, cross_in_b + l * 3 * DD,
                  nullptr, g_t1, DD, 0, xs, gw, lane, 0, 0, 0);
            gsync();

            if (gw < NSEQ * HH) {
                int n = gw / HH, h = gw % HH, b = n / BEAMW;
                const float4* q4 = (const float4*)(g_t1 + n * DD + h * DHH);
                float sc[4];
#pragma unroll
                for (int jj = 0; jj < 4; jj++) {
                    int j = lane + 32 * jj;
                    const float4* k4 = (const float4*)(&g_crossKV[l][b * SSL + j][h * DHH]);
                    float d = 0.f;
#pragma unroll
                    for (int i = 0; i < 16; i++) {
                        float4 a = q4[i], bb4 = k4[i];
                        d += a.x * bb4.x + a.y * bb4.y + a.z * bb4.z + a.w * bb4.w;
                    }
                    sc[jj] = (source_mask[b * SSL + j] == 0) ? -1e9f : d * 0.125f;
                }
                float mx = wmax(fmaxf(fmaxf(sc[0], sc[1]), fmaxf(sc[2], sc[3])));
                float e0 = expf(sc[0] - mx), e1 = expf(sc[1] - mx);
                float e2 = expf(sc[2] - mx), e3 = expf(sc[3] - mx);
                float inv = 1.f / wsum(e0 + e1 + e2 + e3);
                float* as = xs + wid * SSL;
                as[lane] = e0 * inv; as[lane + 32] = e1 * inv;
                as[lane + 64] = e2 * inv; as[lane + 96] = e3 * inv;
                __syncwarp();
                float o0 = 0.f, o1 = 0.f;
                for (int j = 0; j < SSL; j++) {
                    float aj = as[j];
                    const float* Vr = &g_crossKV[l][b * SSL + j][DD + h * DHH];
                    o0 += aj * Vr[lane]; o1 += aj * Vr[lane + 32];
                }
                g_attn[n][h * DHH + lane] = o0;
                g_attn[n][h * DHH + lane + 32] = o1;
            }
            gsync();

            stage20(&g_attn[0][0], xs);
            gemmA(cross_out_w + (size_t)l * DD * DD, cross_out_b + l * DD,
                  &g_x[0][0], &g_y[0][0], DD, 0, xs, gw, lane, 0, 0, 0);
            gsync();
            if (gw < NSEQ) ln_warp(&g_y[gw][0], ln2_g + l * DD, ln2_b + l * DD, &g_x[gw][0], lane);
            gsync();

            stage20(&g_x[0][0], xs);
            gemmA(ff1_w + (size_t)l * DFFL * DD, ff1_b + l * DFFL,
                  nullptr, g_t1, DFFL, 1, xs, gw, lane, 0, 0, 0);
            gsync();
            gemm_ff2(ff2_w + (size_t)l * DD * DFFL, ff2_b + l * DD,
                     &g_x[0][0], &g_y[0][0], xs, gw, lane, tid);
            gsync();
            if (gw < NSEQ) ln_warp(&g_y[gw][0], ln3_g + l * DD, ln3_b + l * DD, &g_x[gw][0], lane);
            gsync();
        }

        stage20(&g_x[0][0], xs);
        gemmA(dense_w, dense_b, nullptr, &g_y[0][0], DD, 2, xs, gw, lane, 0, 0, 0);
        gsync();

        stage20(&g_y[0][0], xs);
        gemmA(emb, nullptr, nullptr, &g_logits[0][0], VV, 0, xs, gw, lane, 0, 0, 0);
        gsync();

        if (bid < NSEQ) {
            int n = bid;
            const float* row = &g_logits[n][0];
            float m = -INFINITY;
            for (int i = tid; i < VV; i += NTHR) m = fmaxf(m, row[i]);
            m = wmax(m);
            if (lane == 0) s_red[wid] = m;
            __syncthreads();
            if (wid == 0) {
                float r = (lane < 8) ? s_red[lane] : -INFINITY;
                if (lane == 0) s_red[0] = wmax(r);
                else wmax(r);
            }
            __syncthreads();
            float mx = s_red[0];
            __syncthreads();
            float s = 0.f;
            for (int i = tid; i < VV; i += NTHR) s += expf(row[i] - mx);
            s = wsum(s);
            if (lane == 0) s_red[wid] = s;
            __syncthreads();
            if (wid == 0) {
                float r = (lane < 8) ? s_red[lane] : 0.f;
                r = wsum(r);
                if (lane == 0) { g_mx[n] = mx; g_lse[n] = logf(r); }
            }
        }
        gsync();

        {   // partial top-k: 37 blocks per batch
            float* mv = xs;
            int* mi = (int*)(xs + NTHR * 5);
            int b2 = bid / 37, sb = bid % 37;
            const int SLI = (BEAMW * VV + 36) / 37;
            int i0 = sb * SLI, i1 = min(BEAMW * VV, i0 + SLI);
            float tv[5]; int ti[5];
#pragma unroll
            for (int q = 0; q < 5; q++) { tv[q] = -INFINITY; ti[q] = 0x7fffffff; }
            for (int i = i0 + tid; i < i1; i += NTHR) {
                int j = i / VV, v = i - j * VV;
                int nn = b2 * BEAMW + j;
                float val = (g_buf[b2][j][t] == TOK_EOS) ? NEGINF
                    : g_scores[b2][j] + g_logits[nn][v] - g_mx[nn] - g_lse[nn];
                ins5(val, i, tv, ti);
            }
#pragma unroll
            for (int q = 0; q < 5; q++) { mv[tid * 5 + q] = tv[q]; mi[tid * 5 + q] = ti[q]; }
            __syncthreads();
            for (int stride = 128; stride >= 1; stride >>= 1) {
                if (tid < stride) {
                    float av[5], bv[5]; int ai[5], bi[5];
#pragma unroll
                    for (int q = 0; q < 5; q++) {
                        av[q] = mv[tid * 5 + q]; ai[q] = mi[tid * 5 + q];
                        bv[q] = mv[(tid + stride) * 5 + q]; bi[q] = mi[(tid + stride) * 5 + q];
                    }
                    int ia = 0, ib = 0;
#pragma unroll
                    for (int q = 0; q < 5; q++) {
                        bool ta = (av[ia] > bv[ib]) || (av[ia] == bv[ib] && ai[ia] < bi[ib]);
                        float rv = ta ? av[ia] : bv[ib];
                        int ri = ta ? ai[ia] : bi[ib];
                        if (ta) ia++; else ib++;
                        mv[tid * 5 + q] = rv; mi[tid * 5 + q] = ri;
                    }
                }
                __syncthreads();
            }
            if (tid < 5) { g_pv[bid * 5 + tid] = mv[tid]; g_pi[bid * 5 + tid] = mi[tid]; }
        }
        gsync();

        if (bid < BB && wid == 0) {   // merge + beam update
            int b = bid;
            float tv[5]; int ti[5];
#pragma unroll
            for (int q = 0; q < 5; q++) { tv[q] = -INFINITY; ti[q] = 0x7fffffff; }
            for (int e = lane; e < 37 * 5; e += 32)
                ins5(g_pv[(b * 37) * 5 + e], g_pi[(b * 37) * 5 + e], tv, ti);
#pragma unroll
            for (int off = 16; off; off >>= 1) {
                float ov[5]; int oi[5];
#pragma unroll
                for (int q = 0; q < 5; q++) {
                    ov[q] = __shfl_xor_sync(0xffffffffu, tv[q], off);
                    oi[q] = __shfl_xor_sync(0xffffffffu, ti[q], off);
                }
                int ia = 0, ib = 0;
                float rv[5]; int ri[5];
#pragma unroll
                for (int q = 0; q < 5; q++) {
                    bool ta = (tv[ia] > ov[ib]) || (tv[ia] == ov[ib] && ti[ia] < oi[ib]);
                    rv[q] = ta ? tv[ia] : ov[ib];
                    ri[q] = ta ? ti[ia] : oi[ib];
                    if (ta) ia++; else ib++;
                }
#pragma unroll
                for (int q = 0; q < 5; q++) { tv[q] = rv[q]; ti[q] = ri[q]; }
            }
            int snap[5];
#pragma unroll
            for (int j = 0; j < 5; j++) snap[j] = (lane < BUFL) ? g_buf[b][j][lane] : 0;
            __syncwarp();
#pragma unroll
            for (int k = 0; k < 5; k++) {
                int id = ti[k], pk = id / VV, tok = id - pk * VV;
                if (lane < BUFL) g_buf[b][k][lane] = (lane == t + 1) ? tok : snap[pk];
                if (lane == 0) { g_scores[b][k] = tv[k]; g_prevK[b][k] = pk; }
            }
        }
        gsync();

        {   // gather KV rows 0..t into pong cache
            int tot = NLL * 2 * NSEQ * (t + 1);
            for (int r = gw; r < tot; r += NWARPT) {
                int j = r % (t + 1), rr = r / (t + 1);
                int n = rr % NSEQ, z = rr / NSEQ;
                int l = z >> 1, kv = z & 1;
                int b = n / BEAMW, k = n % BEAMW;
                int src = b * BEAMW + g_prevK[b][k];
                const float4* s; float4* d;
                if (kv == 0) { s = (const float4*)&g_cacheK[pp][l][src][j][0]; d = (float4*)&g_cacheK[1 - pp][l][n][j][0]; }
                else         { s = (const float4*)&g_cacheV[pp][l][src][j][0]; d = (float4*)&g_cacheV[1 - pp][l][n][j][0]; }
#pragma unroll
                for (int i = 0; i < 6; i++) d[lane + 32 * i] = s[lane + 32 * i];
            }
        }
        gsync();
        pp ^= 1;
    }

    if (bid == 0 && tid < BB * BEAMW) {
        int b = tid / BEAMW, k = tid % BEAMW;
        outbuf[tid] = g_scores[b][k];
        int cum = 0;
        for (int i = 1; i <= TMAXX; i++) {
            int tok = g_buf[b][k][i];
            if (tok == TOK_EOS) cum++;
            outbuf[BB * BEAMW + tid * TMAXX + (i - 1)] = (cum == 0) ? (float)tok : 0.f;
        }
    }
}

extern "C" void kernel_launch(void* const* d_in, const int* in_sizes, int n_in,
                              void* d_out, int out_size) {
    (void)in_sizes; (void)n_in; (void)out_size;
    static int configured = 0;
    if (!configured) {
        cudaFuncSetAttribute(decode_all, cudaFuncAttributeMaxDynamicSharedMemorySize, NSEQ * DD * 4);
        configured = 1;
    }
    decode_all<<<NBLK, NTHR, NSEQ * DD * 4>>>(
        (const float*)d_in[0], (const float*)d_in[1], (const float*)d_in[2], (const float*)d_in[3],
        (const float*)d_in[4], (const float*)d_in[5], (const float*)d_in[6], (const float*)d_in[7],
        (const float*)d_in[8], (const float*)d_in[9], (const float*)d_in[10], (const float*)d_in[11],
        (const float*)d_in[12], (const float*)d_in[13], (const float*)d_in[14], (const float*)d_in[15],
        (const float*)d_in[16], (const float*)d_in[17], (const float*)d_in[18], (const float*)d_in[19],
        (const float*)d_in[20], (const float*)d_in[21], (const float*)d_in[22], (const float*)d_in[23],
        (const float*)d_in[24], (const int*)d_in[25], (float*)d_out);
}

// round 13
// speedup vs baseline: 2.2435x; 1.5974x over previous
#include <cuda_runtime.h>
#include <math.h>

#define BB 4
#define BEAMW 5
#define NSEQ 20
#define TMAXX 16
#define BUFL 17
#define VV 50257
#define DD 768
#define HH 12
#define DHH 64
#define NLL 2
#define SSL 128
#define DFFL 3072
#define TOK_SOS 1
#define TOK_EOS 2
#define NEGINF (-1e20f)
#define NBLK 148
#define NTHR 512
#define NWARP 16
#define NWARPT (NBLK * NWARP)

__device__ float g_x[NSEQ][DD];
__device__ float g_y[NSEQ][DD];
__device__ float g_attn[NSEQ][DD];
__device__ float g_t1[NSEQ * DFFL];
__device__ float g_logits[NSEQ][VV];
__device__ float g_mx[NSEQ];
__device__ float g_lse[NSEQ];
__device__ float g_cacheK[2][NLL][NSEQ][BUFL][DD];
__device__ float g_cacheV[2][NLL][NSEQ][BUFL][DD];
__device__ float g_crossKV[NLL][BB * SSL][2 * DD];
__device__ int   g_buf[BB][BEAMW][BUFL];
__device__ float g_scores[BB][BEAMW];
__device__ int   g_prevK[BB][BEAMW];
__device__ float g_pv[NBLK * 5];
__device__ int   g_pi[NBLK * 5];
__device__ unsigned g_cnt;
__device__ unsigned g_gen;

// CG-style acq/rel grid barrier: no full fence, no L1 flush
__device__ __forceinline__ void gsync() {
    __syncthreads();
    if (threadIdx.x == 0) {
        unsigned gen;
        asm volatile("ld.acquire.gpu.u32 %0, [%1];" : "=r"(gen) : "l"(&g_gen) : "memory");
        unsigned old;
        asm volatile("atom.acq_rel.gpu.add.u32 %0, [%1], %2;"
                     : "=r"(old) : "l"(&g_cnt), "r"(1u) : "memory");
        if (old == NBLK - 1u) {
            asm volatile("st.relaxed.gpu.u32 [%0], %1;" :: "l"(&g_cnt), "r"(0u) : "memory");
            asm volatile("red.release.gpu.add.u32 [%0], %1;" :: "l"(&g_gen), "r"(1u) : "memory");
        } else {
            unsigned cur;
            do {
                __nanosleep(32);
                asm volatile("ld.acquire.gpu.u32 %0, [%1];" : "=r"(cur) : "l"(&g_gen) : "memory");
            } while (cur == gen);
        }
    }
    __syncthreads();
}

__device__ __forceinline__ float wsum(float a) {
#pragma unroll
    for (int o = 16; o; o >>= 1) a += __shfl_xor_sync(0xffffffffu, a, o);
    return a;
}
__device__ __forceinline__ float wmax(float a) {
#pragma unroll
    for (int o = 16; o; o >>= 1) a = fmaxf(a, __shfl_xor_sync(0xffffffffu, a, o));
    return a;
}
__device__ __forceinline__ float dot24(const float4* __restrict__ xr, int lane,
    float4 w0, float4 w1, float4 w2, float4 w3, float4 w4, float4 w5)
{
    float4 x0 = xr[lane], x1 = xr[lane + 32], x2 = xr[lane + 64];
    float4 x3 = xr[lane + 96], x4 = xr[lane + 128], x5 = xr[lane + 160];
    float a = x0.x * w0.x + x0.y * w0.y + x0.z * w0.z + x0.w * w0.w;
    a += x1.x * w1.x + x1.y * w1.y + x1.z * w1.z + x1.w * w1.w;
    a += x2.x * w2.x + x2.y * w2.y + x2.z * w2.z + x2.w * w2.w;
    a += x3.x * w3.x + x3.y * w3.y + x3.z * w3.z + x3.w * w3.w;
    a += x4.x * w4.x + x4.y * w4.y + x4.z * w4.z + x4.w * w4.w;
    a += x5.x * w5.x + x5.y * w5.y + x5.z * w5.z + x5.w * w5.w;
    return a;
}

__device__ __forceinline__ void stage_plain(const float* __restrict__ X, float* xs) {
    const float4* s = (const float4*)X;
    float4* d = (float4*)xs;
    for (int i = threadIdx.x; i < NSEQ * 192; i += NTHR) d[i] = s[i];
    __syncthreads();
}

// fused: stage LN(y) into xs; block 0 also publishes to g_x (residual source)
__device__ __forceinline__ void stage_ln(const float* __restrict__ y,
    const float* __restrict__ gg, const float* __restrict__ bb2,
    float* xs, int wgx, int lane, int wid, int bid)
{
    for (int n = wid; n < NSEQ; n += NWARP) {
        const float* yr = y + n * DD;
        float v[24]; float s = 0.f;
#pragma unroll
        for (int j = 0; j < 24; j++) { v[j] = yr[lane + 32 * j]; s += v[j]; }
        float mean = wsum(s) * (1.f / DD);
        float q = 0.f;
#pragma unroll
        for (int j = 0; j < 24; j++) { float d = v[j] - mean; q += d * d; }
        float rstd = rsqrtf(wsum(q) * (1.f / DD) + 1e-5f);
#pragma unroll
        for (int j = 0; j < 24; j++) {
            int k = lane + 32 * j;
            float o = (v[j] - mean) * rstd * gg[k] + bb2[k];
            xs[n * DD + k] = o;
            if (wgx && bid == 0) g_x[n][k] = o;
        }
    }
    __syncthreads();
}

__device__ __forceinline__ void stage_embed_ln(const float* __restrict__ emb,
    const float* __restrict__ pos, const float* __restrict__ gg,
    const float* __restrict__ bb2, int t, float* xs, int lane, int wid, int bid)
{
    for (int n = wid; n < NSEQ; n += NWARP) {
        int tok = g_buf[n / BEAMW][n % BEAMW][t];
        float v[24]; float s = 0.f;
#pragma unroll
        for (int j = 0; j < 24; j++) {
            int k = lane + 32 * j;
            v[j] = emb[(size_t)tok * DD + k] + pos[(size_t)t * DD + k];
            s += v[j];
        }
        float mean = wsum(s) * (1.f / DD);
        float q = 0.f;
#pragma unroll
        for (int j = 0; j < 24; j++) { float d = v[j] - mean; q += d * d; }
        float rstd = rsqrtf(wsum(q) * (1.f / DD) + 1e-5f);
#pragma unroll
        for (int j = 0; j < 24; j++) {
            int k = lane + 32 * j;
            float o = (v[j] - mean) * rstd * gg[k] + bb2[k];
            xs[n * DD + k] = o;
            if (bid == 0) g_x[n][k] = o;
        }
    }
    __syncthreads();
}

// warp-per-column GEMM (small M): out[20][M] = epi(xs @ W^T + b)(+resid); epi3 = qkv routing
__device__ void gemmA(const float* __restrict__ W, const float* __restrict__ bias,
    const float* __restrict__ resid, float* __restrict__ out, int M, int epi,
    const float* xs, int gw, int lane, int l, int t, int pp)
{
    for (int m = gw; m < M; m += NWARPT) {
        const float4* Wr = (const float4*)(W + (size_t)m * DD);
        float4 w0 = Wr[lane], w1 = Wr[lane + 32], w2 = Wr[lane + 64];
        float4 w3 = Wr[lane + 96], w4 = Wr[lane + 128], w5 = Wr[lane + 160];
        float bv = bias ? bias[m] : 0.f;
        float acc[NSEQ];
#pragma unroll
        for (int n = 0; n < NSEQ; n++)
            acc[n] = wsum(dot24((const float4*)xs + n * 192, lane, w0, w1, w2, w3, w4, w5));
#pragma unroll
        for (int n = 0; n < NSEQ; n++) if (lane == n) {
            float s = acc[n] + bv;
            if (epi == 1) s = fmaxf(s, 0.f);
            else if (epi == 2) s = tanhf(s);
            if (resid) s += resid[n * DD + m];
            if (epi == 3) {
                if (m < DD)          g_t1[n * DD + m] = s;
                else if (m < 2 * DD) g_cacheK[pp][l][n][t][m - DD] = s;
                else                 g_cacheV[pp][l][n][t][m - 2 * DD] = s;
            } else out[(size_t)n * M + m] = s;
        }
    }
}

__device__ void gemm_ff2(const float* __restrict__ W, const float* __restrict__ bias,
    const float* __restrict__ resid, float* __restrict__ out, float* xs,
    int gw, int lane, int tid)
{
    int m = gw;
    bool act = (m < DD);
    float acc[NSEQ];
#pragma unroll
    for (int n = 0; n < NSEQ; n++) acc[n] = 0.f;
    const float4* Wr = (const float4*)(W + (act ? (size_t)m * DFFL : 0));
    for (int c = 0; c < 4; c++) {
        __syncthreads();
        for (int i = tid; i < NSEQ * 192; i += NTHR) {
            int n = i / 192, k = i - n * 192;
            ((float4*)xs)[i] = ((const float4*)(g_t1 + n * DFFL + c * DD))[k];
        }
        __syncthreads();
        if (act) {
            float4 w0 = Wr[c * 192 + lane], w1 = Wr[c * 192 + lane + 32], w2 = Wr[c * 192 + lane + 64];
            float4 w3 = Wr[c * 192 + lane + 96], w4 = Wr[c * 192 + lane + 128], w5 = Wr[c * 192 + lane + 160];
#pragma unroll
            for (int n = 0; n < NSEQ; n++)
                acc[n] += dot24((const float4*)xs + n * 192, lane, w0, w1, w2, w3, w4, w5);
        }
    }
    if (act) {
#pragma unroll
        for (int n = 0; n < NSEQ; n++) {
            float a = wsum(acc[n]);
            if (lane == n) out[n * DD + m] = a + bias[m] + resid[n * DD + m];
        }
    }
}

// ---- logits: thread-per-column with packed f32x2 FMA ----
__device__ __forceinline__ void stage_pairs(const float* __restrict__ src, float* xs) {
    float2* d = (float2*)xs;   // layout [k][j] : (src[2j][k], src[2j+1][k])
    for (int i = threadIdx.x; i < DD * 10; i += NTHR) {
        int k = i / 10, j = i - (i / 10) * 10;
        float2 p;
        p.x = src[(2 * j) * DD + k];
        p.y = src[(2 * j + 1) * DD + k];
        d[i] = p;
    }
    __syncthreads();
}

__device__ __forceinline__ void fma10(float w, const unsigned long long* __restrict__ xk,
                                      unsigned long long* acc)
{
    unsigned long long wp;
    asm("mov.b64 %0, {%1, %1};" : "=l"(wp) : "f"(w));
    ulonglong2 a0 = *(const ulonglong2*)(xk + 0);
    ulonglong2 a1 = *(const ulonglong2*)(xk + 2);
    ulonglong2 a2 = *(const ulonglong2*)(xk + 4);
    ulonglong2 a3 = *(const ulonglong2*)(xk + 6);
    ulonglong2 a4 = *(const ulonglong2*)(xk + 8);
    asm("fma.rn.f32x2 %0, %1, %2, %0;" : "+l"(acc[0]) : "l"(a0.x), "l"(wp));
    asm("fma.rn.f32x2 %0, %1, %2, %0;" : "+l"(acc[1]) : "l"(a0.y), "l"(wp));
    asm("fma.rn.f32x2 %0, %1, %2, %0;" : "+l"(acc[2]) : "l"(a1.x), "l"(wp));
    asm("fma.rn.f32x2 %0, %1, %2, %0;" : "+l"(acc[3]) : "l"(a1.y), "l"(wp));
    asm("fma.rn.f32x2 %0, %1, %2, %0;" : "+l"(acc[4]) : "l"(a2.x), "l"(wp));
    asm("fma.rn.f32x2 %0, %1, %2, %0;" : "+l"(acc[5]) : "l"(a2.y), "l"(wp));
    asm("fma.rn.f32x2 %0, %1, %2, %0;" : "+l"(acc[6]) : "l"(a3.x), "l"(wp));
    asm("fma.rn.f32x2 %0, %1, %2, %0;" : "+l"(acc[7]) : "l"(a3.y), "l"(wp));
    asm("fma.rn.f32x2 %0, %1, %2, %0;" : "+l"(acc[8]) : "l"(a4.x), "l"(wp));
    asm("fma.rn.f32x2 %0, %1, %2, %0;" : "+l"(acc[9]) : "l"(a4.y), "l"(wp));
}

__device__ void gemm_logits(const float* __restrict__ emb, const float* xs, int bid, int tid) {
    int m = bid * NTHR + tid;
    if (m >= VV) return;
    unsigned long long acc[10];
#pragma unroll
    for (int j = 0; j < 10; j++) acc[j] = 0ull;
    const float4* Wr = (const float4*)(emb + (size_t)m * DD);
    const unsigned long long* xp = (const unsigned long long*)xs;
#pragma unroll 2
    for (int kq = 0; kq < 192; kq++) {
        float4 w = Wr[kq];
        const unsigned long long* x0 = xp + (kq * 4) * 10;
        fma10(w.x, x0, acc);
        fma10(w.y, x0 + 10, acc);
        fma10(w.z, x0 + 20, acc);
        fma10(w.w, x0 + 30, acc);
    }
#pragma unroll
    for (int j = 0; j < 10; j++) {
        float lo, hi;
        asm("mov.b64 {%0, %1}, %2;" : "=f"(lo), "=f"(hi) : "l"(acc[j]));
        g_logits[2 * j][m] = lo;
        g_logits[2 * j + 1][m] = hi;
    }
}

__device__ __forceinline__ void ins5(float v, int id, float* tv, int* ti) {
    if (v > tv[4] || (v == tv[4] && id < ti[4])) {
        int p = 4;
        while (p > 0 && (v > tv[p - 1] || (v == tv[p - 1] && id < ti[p - 1]))) {
            tv[p] = tv[p - 1]; ti[p] = ti[p - 1]; p--;
        }
        tv[p] = v; ti[p] = id;
    }
}

__global__ void __launch_bounds__(NTHR, 1) decode_all(
    const float* __restrict__ emb, const float* __restrict__ pos,
    const float* __restrict__ ln_emb_g, const float* __restrict__ ln_emb_b,
    const float* __restrict__ self_in_w, const float* __restrict__ self_in_b,
    const float* __restrict__ self_out_w, const float* __restrict__ self_out_b,
    const float* __restrict__ cross_in_w, const float* __restrict__ cross_in_b,
    const float* __restrict__ cross_out_w, const float* __restrict__ cross_out_b,
    const float* __restrict__ ff1_w, const float* __restrict__ ff1_b,
    const float* __restrict__ ff2_w, const float* __restrict__ ff2_b,
    const float* __restrict__ ln1_g, const float* __restrict__ ln1_b,
    const float* __restrict__ ln2_g, const float* __restrict__ ln2_b,
    const float* __restrict__ ln3_g, const float* __restrict__ ln3_b,
    const float* __restrict__ dense_w, const float* __restrict__ dense_b,
    const float* __restrict__ context, const int* __restrict__ source_mask,
    float* __restrict__ outbuf)
{
    extern __shared__ float xs[];
    __shared__ float s_red[NWARP];
    const int tid = threadIdx.x, lane = tid & 31, wid = tid >> 5, bid = blockIdx.x;
    const int gw = bid * NWARP + wid;

    if (bid == 0) {
        if (tid < BB * BEAMW * BUFL) {
            int b = tid / (BEAMW * BUFL), r = tid % (BEAMW * BUFL), k = r / BUFL, p = r % BUFL;
            g_buf[b][k][p] = (k == 0 && p == 0) ? TOK_SOS : 0;
        }
        if (tid < BB * BEAMW) ((float*)g_scores)[tid] = (tid % BEAMW == 0) ? 0.f : NEGINF;
    }

    // crossKV precompute: 96 tasks of 32 columns
    for (int task = bid; task < 2 * 48; task += NBLK) {
        int l = task / 48, mt = task % 48;
        for (int nt = 0; nt < 26; nt++) {
            int base = nt * 20;
            int nr = min(20, BB * SSL - base);
            __syncthreads();
            {
                const float4* s = (const float4*)(context + (size_t)base * DD);
                for (int i = tid; i < nr * 192; i += NTHR) ((float4*)xs)[i] = s[i];
            }
            __syncthreads();
#pragma unroll
            for (int c = 0; c < 2; c++) {
                int m = mt * 32 + wid * 2 + c;
                const float4* Wr = (const float4*)(cross_in_w + (size_t)l * 3 * DD * DD + (size_t)(DD + m) * DD);
                float4 w0 = Wr[lane], w1 = Wr[lane + 32], w2 = Wr[lane + 64];
                float4 w3 = Wr[lane + 96], w4 = Wr[lane + 128], w5 = Wr[lane + 160];
                float bv = cross_in_b[l * 3 * DD + DD + m];
#pragma unroll
                for (int n = 0; n < 20; n++) {
                    float a = wsum(dot24((const float4*)xs + n * 192, lane, w0, w1, w2, w3, w4, w5));
                    if (n < nr && lane == n) g_crossKV[l][base + n][m] = a + bv;
                }
            }
        }
    }
    gsync();

    int pp = 0;
    for (int t = 0; t < TMAXX; t++) {
        for (int l = 0; l < NLL; l++) {
            // P1: embed/ln3 staging fused + qkv
            if (l == 0) stage_embed_ln(emb, pos, ln_emb_g, ln_emb_b, t, xs, lane, wid, bid);
            else        stage_ln(&g_y[0][0], ln3_g + (l - 1) * DD, ln3_b + (l - 1) * DD, xs, 1, lane, wid, bid);
            gemmA(self_in_w + (size_t)l * 3 * DD * DD, self_in_b + l * 3 * DD,
                  nullptr, nullptr, 3 * DD, 3, xs, gw, lane, l, t, pp);
            gsync();

            // P2: self-attention
            if (gw < NSEQ * HH) {
                int n = gw / HH, h = gw % HH;
                const float4* q4 = (const float4*)(g_t1 + n * DD + h * DHH);
                bool actj = (lane <= t);
                float dq = 0.f;
                if (actj) {
                    const float4* k4 = (const float4*)(&g_cacheK[pp][l][n][lane][h * DHH]);
#pragma unroll
                    for (int i = 0; i < 16; i++) {
                        float4 a = q4[i], b = k4[i];
                        dq += a.x * b.x + a.y * b.y + a.z * b.z + a.w * b.w;
                    }
                }
                float sc = actj ? dq * 0.125f : -INFINITY;
                float mx = wmax(sc);
                float e = actj ? expf(sc - mx) : 0.f;
                float aw = e / wsum(e);
                float o0 = 0.f, o1 = 0.f;
                for (int j = 0; j <= t; j++) {
                    float aj = __shfl_sync(0xffffffffu, aw, j);
                    const float* Vr = &g_cacheV[pp][l][n][j][h * DHH];
                    o0 += aj * Vr[lane]; o1 += aj * Vr[lane + 32];
                }
                g_attn[n][h * DHH + lane] = o0;
                g_attn[n][h * DHH + lane + 32] = o1;
            }
            gsync();

            // P3: self_out + resid
            stage_plain(&g_attn[0][0], xs);
            gemmA(self_out_w + (size_t)l * DD * DD, self_out_b + l * DD,
                  &g_x[0][0], &g_y[0][0], DD, 0, xs, gw, lane, 0, 0, 0);
            gsync();

            // P4: ln1 fused + cross q
            stage_ln(&g_y[0][0], ln1_g + l * DD, ln1_b + l * DD, xs, 1, lane, wid, bid);
            gemmA(cross_in_w + (size_t)l * 3 * DD * DD, cross_in_b + l * 3 * DD,
                  nullptr, g_t1, DD, 0, xs, gw, lane, 0, 0, 0);
            gsync();

            // P5: cross-attention
            if (gw < NSEQ * HH) {
                int n = gw / HH, h = gw % HH, b = n / BEAMW;
                const float4* q4 = (const float4*)(g_t1 + n * DD + h * DHH);
                float sc[4];
#pragma unroll
                for (int jj = 0; jj < 4; jj++) {
                    int j = lane + 32 * jj;
                    const float4* k4 = (const float4*)(&g_crossKV[l][b * SSL + j][h * DHH]);
                    float d = 0.f;
#pragma unroll
                    for (int i = 0; i < 16; i++) {
                        float4 a = q4[i], bb4 = k4[i];
                        d += a.x * bb4.x + a.y * bb4.y + a.z * bb4.z + a.w * bb4.w;
                    }
                    sc[jj] = (source_mask[b * SSL + j] == 0) ? -1e9f : d * 0.125f;
                }
                float mx = wmax(fmaxf(fmaxf(sc[0], sc[1]), fmaxf(sc[2], sc[3])));
                float e0 = expf(sc[0] - mx), e1 = expf(sc[1] - mx);
                float e2 = expf(sc[2] - mx), e3 = expf(sc[3] - mx);
                float inv = 1.f / wsum(e0 + e1 + e2 + e3);
                float* as = xs + wid * SSL;
                as[lane] = e0 * inv; as[lane + 32] = e1 * inv;
                as[lane + 64] = e2 * inv; as[lane + 96] = e3 * inv;
                __syncwarp();
                float o0 = 0.f, o1 = 0.f;
                for (int j = 0; j < SSL; j++) {
                    float aj = as[j];
                    const float* Vr = &g_crossKV[l][b * SSL + j][DD + h * DHH];
                    o0 += aj * Vr[lane]; o1 += aj * Vr[lane + 32];
                }
                g_attn[n][h * DHH + lane] = o0;
                g_attn[n][h * DHH + lane + 32] = o1;
            }
            gsync();

            // P6: cross_out + resid
            stage_plain(&g_attn[0][0], xs);
            gemmA(cross_out_w + (size_t)l * DD * DD, cross_out_b + l * DD,
                  &g_x[0][0], &g_y[0][0], DD, 0, xs, gw, lane, 0, 0, 0);
            gsync();

            // P7: ln2 fused + ff1
            stage_ln(&g_y[0][0], ln2_g + l * DD, ln2_b + l * DD, xs, 1, lane, wid, bid);
            gemmA(ff1_w + (size_t)l * DFFL * DD, ff1_b + l * DFFL,
                  nullptr, g_t1, DFFL, 1, xs, gw, lane, 0, 0, 0);
            gsync();

            // P8: ff2 + resid
            gemm_ff2(ff2_w + (size_t)l * DD * DFFL, ff2_b + l * DD,
                     &g_x[0][0], &g_y[0][0], xs, gw, lane, tid);
            gsync();
        }

        // dense (tanh) -> g_attn
        stage_ln(&g_y[0][0], ln3_g + (NLL - 1) * DD, ln3_b + (NLL - 1) * DD, xs, 0, lane, wid, bid);
        gemmA(dense_w, dense_b, nullptr, &g_attn[0][0], DD, 2, xs, gw, lane, 0, 0, 0);
        gsync();

        // logits
        stage_pairs(&g_attn[0][0], xs);
        gemm_logits(emb, xs, bid, tid);
        gsync();

        // lse
        if (bid < NSEQ) {
            int n = bid;
            const float* row = &g_logits[n][0];
            float m = -INFINITY;
            for (int i = tid; i < VV; i += NTHR) m = fmaxf(m, row[i]);
            m = wmax(m);
            if (lane == 0) s_red[wid] = m;
            __syncthreads();
            if (wid == 0) {
                float r = (lane < NWARP) ? s_red[lane] : -INFINITY;
                r = wmax(r);
                if (lane == 0) s_red[0] = r;
            }
            __syncthreads();
            float mx = s_red[0];
            __syncthreads();
            float s = 0.f;
            for (int i = tid; i < VV; i += NTHR) s += expf(row[i] - mx);
            s = wsum(s);
            if (lane == 0) s_red[wid] = s;
            __syncthreads();
            if (wid == 0) {
                float r = (lane < NWARP) ? s_red[lane] : 0.f;
                r = wsum(r);
                if (lane == 0) { g_mx[n] = mx; g_lse[n] = logf(r); }
            }
        }
        gsync();

        {   // partial top-k: 37 blocks per batch
            float* mv = xs;
            int* mi = (int*)(xs + NTHR * 5);
            int b2 = bid / 37, sb = bid % 37;
            const int SLI = (BEAMW * VV + 36) / 37;
            int i0 = sb * SLI, i1 = min(BEAMW * VV, i0 + SLI);
            float tv[5]; int ti[5];
#pragma unroll
            for (int q = 0; q < 5; q++) { tv[q] = -INFINITY; ti[q] = 0x7fffffff; }
            for (int i = i0 + tid; i < i1; i += NTHR) {
                int j = i / VV, v = i - j * VV;
                int nn = b2 * BEAMW + j;
                float val = (g_buf[b2][j][t] == TOK_EOS) ? NEGINF
                    : g_scores[b2][j] + g_logits[nn][v] - g_mx[nn] - g_lse[nn];
                ins5(val, i, tv, ti);
            }
#pragma unroll
            for (int q = 0; q < 5; q++) { mv[tid * 5 + q] = tv[q]; mi[tid * 5 + q] = ti[q]; }
            __syncthreads();
            for (int stride = NTHR / 2; stride >= 1; stride >>= 1) {
                if (tid < stride) {
                    float av[5], bv[5]; int ai[5], bi[5];
#pragma unroll
                    for (int q = 0; q < 5; q++) {
                        av[q] = mv[tid * 5 + q]; ai[q] = mi[tid * 5 + q];
                        bv[q] = mv[(tid + stride) * 5 + q]; bi[q] = mi[(tid + stride) * 5 + q];
                    }
                    int ia = 0, ib = 0;
#pragma unroll
                    for (int q = 0; q < 5; q++) {
                        bool ta = (av[ia] > bv[ib]) || (av[ia] == bv[ib] && ai[ia] < bi[ib]);
                        float rv = ta ? av[ia] : bv[ib];
                        int ri = ta ? ai[ia] : bi[ib];
                        if (ta) ia++; else ib++;
                        mv[tid * 5 + q] = rv; mi[tid * 5 + q] = ri;
                    }
                }
                __syncthreads();
            }
            if (tid < 5) { g_pv[bid * 5 + tid] = mv[tid]; g_pi[bid * 5 + tid] = mi[tid]; }
        }
        gsync();

        if (bid < BB && wid == 0) {   // merge + beam update
            int b = bid;
            float tv[5]; int ti[5];
#pragma unroll
            for (int q = 0; q < 5; q++) { tv[q] = -INFINITY; ti[q] = 0x7fffffff; }
            for (int e = lane; e < 37 * 5; e += 32)
                ins5(g_pv[(b * 37) * 5 + e], g_pi[(b * 37) * 5 + e], tv, ti);
#pragma unroll
            for (int off = 16; off; off >>= 1) {
                float ov[5]; int oi[5];
#pragma unroll
                for (int q = 0; q < 5; q++) {
                    ov[q] = __shfl_xor_sync(0xffffffffu, tv[q], off);
                    oi[q] = __shfl_xor_sync(0xffffffffu, ti[q], off);
                }
                int ia = 0, ib = 0;
                float rv[5]; int ri[5];
#pragma unroll
                for (int q = 0; q < 5; q++) {
                    bool ta = (tv[ia] > ov[ib]) || (tv[ia] == ov[ib] && ti[ia] < oi[ib]);
                    rv[q] = ta ? tv[ia] : ov[ib];
                    ri[q] = ta ? ti[ia] : oi[ib];
                    if (ta) ia++; else ib++;
                }
#pragma unroll
                for (int q = 0; q < 5; q++) { tv[q] = rv[q]; ti[q] = ri[q]; }
            }
            int snap[5];
#pragma unroll
            for (int j = 0; j < 5; j++) snap[j] = (lane < BUFL) ? g_buf[b][j][lane] : 0;
            __syncwarp();
#pragma unroll
            for (int k = 0; k < 5; k++) {
                int id = ti[k], pk = id / VV, tok = id - pk * VV;
                if (lane < BUFL) g_buf[b][k][lane] = (lane == t + 1) ? tok : snap[pk];
                if (lane == 0) { g_scores[b][k] = tv[k]; g_prevK[b][k] = pk; }
            }
        }
        gsync();

        {   // gather KV rows 0..t into pong cache
            int tot = NLL * 2 * NSEQ * (t + 1);
            for (int r = gw; r < tot; r += NWARPT) {
                int j = r % (t + 1), rr = r / (t + 1);
                int n = rr % NSEQ, z = rr / NSEQ;
                int l = z >> 1, kv = z & 1;
                int b = n / BEAMW, k = n % BEAMW;
                int src = b * BEAMW + g_prevK[b][k];
                const float4* s; float4* d;
                if (kv == 0) { s = (const float4*)&g_cacheK[pp][l][src][j][0]; d = (float4*)&g_cacheK[1 - pp][l][n][j][0]; }
                else         { s = (const float4*)&g_cacheV[pp][l][src][j][0]; d = (float4*)&g_cacheV[1 - pp][l][n][j][0]; }
#pragma unroll
                for (int i = 0; i < 6; i++) d[lane + 32 * i] = s[lane + 32 * i];
            }
        }
        gsync();
        pp ^= 1;
    }

    if (bid == 0 && tid < BB * BEAMW) {
        int b = tid / BEAMW, k = tid % BEAMW;
        outbuf[tid] = g_scores[b][k];
        int cum = 0;
        for (int i = 1; i <= TMAXX; i++) {
            int tok = g_buf[b][k][i];
            if (tok == TOK_EOS) cum++;
            outbuf[BB * BEAMW + tid * TMAXX + (i - 1)] = (cum == 0) ? (float)tok : 0.f;
        }
    }
}

extern "C" void kernel_launch(void* const* d_in, const int* in_sizes, int n_in,
                              void* d_out, int out_size) {
    (void)in_sizes; (void)n_in; (void)out_size;
    cudaFuncSetAttribute(decode_all, cudaFuncAttributeMaxDynamicSharedMemorySize, NSEQ * DD * 4);
    decode_all<<<NBLK, NTHR, NSEQ * DD * 4>>>(
        (const float*)d_in[0], (const float*)d_in[1], (const float*)d_in[2], (const float*)d_in[3],
        (const float*)d_in[4], (const float*)d_in[5], (const float*)d_in[6], (const float*)d_in[7],
        (const float*)d_in[8], (const float*)d_in[9], (const float*)d_in[10], (const float*)d_in[11],
        (const float*)d_in[12], (const float*)d_in[13], (const float*)d_in[14], (const float*)d_in[15],
        (const float*)d_in[16], (const float*)d_in[17], (const float*)d_in[18], (const float*)d_in[19],
        (const float*)d_in[20], (const float*)d_in[21], (const float*)d_in[22], (const float*)d_in[23],
        (const float*)d_in[24], (const int*)d_in[25], (float*)d_out);
}

// round 17
// speedup vs baseline: 2.2835x; 1.0178x over previous
#include <cuda_runtime.h>
#include <math.h>

#define BB 4
#define BEAMW 5
#define NSEQ 20
#define TMAXX 16
#define BUFL 17
#define VV 50257
#define DD 768
#define HH 12
#define DHH 64
#define NLL 2
#define SSL 128
#define DFFL 3072
#define TOK_SOS 1
#define TOK_EOS 2
#define NEGINF (-1e20f)
#define NBLK 148
#define NTHR 512
#define NWARP 16
#define NWARPT (NBLK * NWARP)

__device__ float g_x[NSEQ][DD];
__device__ float g_y[NSEQ][DD];
__device__ float g_attn[NSEQ][DD];
__device__ float g_t1[NSEQ * DFFL];
__device__ float g_logits[NSEQ][VV];
__device__ float g_mx[NSEQ];
__device__ float g_lse[NSEQ];
__device__ float g_cacheK[NLL][NSEQ][BUFL][DD];
__device__ float g_cacheV[NLL][NSEQ][BUFL][DD];
__device__ float g_crossKV[NLL][BB * SSL][2 * DD];
__device__ int   g_buf[BB][BEAMW][BUFL];
__device__ int   g_anc[NSEQ][BUFL];
__device__ float g_scores[BB][BEAMW];
__device__ float g_pv[NBLK * 5];
__device__ int   g_pi[NBLK * 5];
__device__ unsigned g_cnt;
__device__ unsigned g_gen;

// acq/rel grid barrier
__device__ __forceinline__ void gsync() {
    __syncthreads();
    if (threadIdx.x == 0) {
        unsigned gen;
        asm volatile("ld.acquire.gpu.u32 %0, [%1];" : "=r"(gen) : "l"(&g_gen) : "memory");
        unsigned old;
        asm volatile("atom.acq_rel.gpu.add.u32 %0, [%1], %2;"
                     : "=r"(old) : "l"(&g_cnt), "r"(1u) : "memory");
        if (old == NBLK - 1u) {
            asm volatile("st.relaxed.gpu.u32 [%0], %1;" :: "l"(&g_cnt), "r"(0u) : "memory");
            asm volatile("red.release.gpu.add.u32 [%0], %1;" :: "l"(&g_gen), "r"(1u) : "memory");
        } else {
            unsigned cur;
            do {
                __nanosleep(32);
                asm volatile("ld.acquire.gpu.u32 %0, [%1];" : "=r"(cur) : "l"(&g_gen) : "memory");
            } while (cur == gen);
        }
    }
    __syncthreads();
}

__device__ __forceinline__ float wsum(float a) {
#pragma unroll
    for (int o = 16; o; o >>= 1) a += __shfl_xor_sync(0xffffffffu, a, o);
    return a;
}
__device__ __forceinline__ float wmax(float a) {
#pragma unroll
    for (int o = 16; o; o >>= 1) a = fmaxf(a, __shfl_xor_sync(0xffffffffu, a, o));
    return a;
}
__device__ __forceinline__ float dot24(const float4* __restrict__ xr, int lane,
    float4 w0, float4 w1, float4 w2, float4 w3, float4 w4, float4 w5)
{
    float4 x0 = xr[lane], x1 = xr[lane + 32], x2 = xr[lane + 64];
    float4 x3 = xr[lane + 96], x4 = xr[lane + 128], x5 = xr[lane + 160];
    float a = x0.x * w0.x + x0.y * w0.y + x0.z * w0.z + x0.w * w0.w;
    a += x1.x * w1.x + x1.y * w1.y + x1.z * w1.z + x1.w * w1.w;
    a += x2.x * w2.x + x2.y * w2.y + x2.z * w2.z + x2.w * w2.w;
    a += x3.x * w3.x + x3.y * w3.y + x3.z * w3.z + x3.w * w3.w;
    a += x4.x * w4.x + x4.y * w4.y + x4.z * w4.z + x4.w * w4.w;
    a += x5.x * w5.x + x5.y * w5.y + x5.z * w5.z + x5.w * w5.w;
    return a;
}

__device__ __forceinline__ void stage_plain(const float* __restrict__ X, float* xs) {
    const float4* s = (const float4*)X;
    float4* d = (float4*)xs;
    for (int i = threadIdx.x; i < NSEQ * 192; i += NTHR) d[i] = s[i];
    __syncthreads();
}

__device__ __forceinline__ void stage_ln(const float* __restrict__ y,
    const float* __restrict__ gg, const float* __restrict__ bb2,
    float* xs, int wgx, int lane, int wid, int bid)
{
    for (int n = wid; n < NSEQ; n += NWARP) {
        const float* yr = y + n * DD;
        float v[24]; float s = 0.f;
#pragma unroll
        for (int j = 0; j < 24; j++) { v[j] = yr[lane + 32 * j]; s += v[j]; }
        float mean = wsum(s) * (1.f / DD);
        float q = 0.f;
#pragma unroll
        for (int j = 0; j < 24; j++) { float d = v[j] - mean; q += d * d; }
        float rstd = rsqrtf(wsum(q) * (1.f / DD) + 1e-5f);
#pragma unroll
        for (int j = 0; j < 24; j++) {
            int k = lane + 32 * j;
            float o = (v[j] - mean) * rstd * gg[k] + bb2[k];
            xs[n * DD + k] = o;
            if (wgx && bid == 0) g_x[n][k] = o;
        }
    }
    __syncthreads();
}

__device__ __forceinline__ void stage_embed_ln(const float* __restrict__ emb,
    const float* __restrict__ pos, const float* __restrict__ gg,
    const float* __restrict__ bb2, int t, float* xs, int lane, int wid, int bid)
{
    for (int n = wid; n < NSEQ; n += NWARP) {
        int tok = g_buf[n / BEAMW][n % BEAMW][t];
        float v[24]; float s = 0.f;
#pragma unroll
        for (int j = 0; j < 24; j++) {
            int k = lane + 32 * j;
            v[j] = emb[(size_t)tok * DD + k] + pos[(size_t)t * DD + k];
            s += v[j];
        }
        float mean = wsum(s) * (1.f / DD);
        float q = 0.f;
#pragma unroll
        for (int j = 0; j < 24; j++) { float d = v[j] - mean; q += d * d; }
        float rstd = rsqrtf(wsum(q) * (1.f / DD) + 1e-5f);
#pragma unroll
        for (int j = 0; j < 24; j++) {
            int k = lane + 32 * j;
            float o = (v[j] - mean) * rstd * gg[k] + bb2[k];
            xs[n * DD + k] = o;
            if (bid == 0) g_x[n][k] = o;
        }
    }
    __syncthreads();
}

// warp-per-column GEMM; epi3 = qkv routing (q->t1, K/V->cache row t)
__device__ void gemmA(const float* __restrict__ W, const float* __restrict__ bias,
    const float* __restrict__ resid, float* __restrict__ out, int M, int epi,
    const float* xs, int gw, int lane, int l, int t)
{
    for (int m = gw; m < M; m += NWARPT) {
        const float4* Wr = (const float4*)(W + (size_t)m * DD);
        float4 w0 = Wr[lane], w1 = Wr[lane + 32], w2 = Wr[lane + 64];
        float4 w3 = Wr[lane + 96], w4 = Wr[lane + 128], w5 = Wr[lane + 160];
        float bv = bias ? bias[m] : 0.f;
        float acc[NSEQ];
#pragma unroll
        for (int n = 0; n < NSEQ; n++)
            acc[n] = wsum(dot24((const float4*)xs + n * 192, lane, w0, w1, w2, w3, w4, w5));
#pragma unroll
        for (int n = 0; n < NSEQ; n++) if (lane == n) {
            float s = acc[n] + bv;
            if (epi == 1) s = fmaxf(s, 0.f);
            else if (epi == 2) s = tanhf(s);
            if (resid) s += resid[n * DD + m];
            if (epi == 3) {
                if (m < DD)          g_t1[n * DD + m] = s;
                else if (m < 2 * DD) g_cacheK[l][n][t][m - DD] = s;
                else                 g_cacheV[l][n][t][m - 2 * DD] = s;
            } else out[(size_t)n * M + m] = s;
        }
    }
}

__device__ void gemm_ff2(const float* __restrict__ W, const float* __restrict__ bias,
    const float* __restrict__ resid, float* __restrict__ out, float* xs,
    int gw, int lane, int tid)
{
    int m = gw;
    bool act = (m < DD);
    float acc[NSEQ];
#pragma unroll
    for (int n = 0; n < NSEQ; n++) acc[n] = 0.f;
    const float4* Wr = (const float4*)(W + (act ? (size_t)m * DFFL : 0));
    for (int c = 0; c < 4; c++) {
        __syncthreads();
        for (int i = tid; i < NSEQ * 192; i += NTHR) {
            int n = i / 192, k = i - n * 192;
            ((float4*)xs)[i] = ((const float4*)(g_t1 + n * DFFL + c * DD))[k];
        }
        __syncthreads();
        if (act) {
            float4 w0 = Wr[c * 192 + lane], w1 = Wr[c * 192 + lane + 32], w2 = Wr[c * 192 + lane + 64];
            float4 w3 = Wr[c * 192 + lane + 96], w4 = Wr[c * 192 + lane + 128], w5 = Wr[c * 192 + lane + 160];
#pragma unroll
            for (int n = 0; n < NSEQ; n++)
                acc[n] += dot24((const float4*)xs + n * 192, lane, w0, w1, w2, w3, w4, w5);
        }
    }
    if (act) {
#pragma unroll
        for (int n = 0; n < NSEQ; n++) {
            float a = wsum(acc[n]);
            if (lane == n) out[n * DD + m] = a + bias[m] + resid[n * DD + m];
        }
    }
}

// ---- logits: thread-per-column, packed f32x2 FMA, prefetched W ----
__device__ __forceinline__ void stage_pairs(const float* __restrict__ src, float* xs) {
    float2* d = (float2*)xs;
    for (int i = threadIdx.x; i < DD * 10; i += NTHR) {
        int k = i / 10, j = i - (i / 10) * 10;
        float2 p;
        p.x = src[(2 * j) * DD + k];
        p.y = src[(2 * j + 1) * DD + k];
        d[i] = p;
    }
    __syncthreads();
}

__device__ __forceinline__ void fma10(float w, const unsigned long long* __restrict__ xk,
                                      unsigned long long* acc)
{
    unsigned long long wp;
    asm("mov.b64 %0, {%1, %1};" : "=l"(wp) : "f"(w));
    ulonglong2 a0 = *(const ulonglong2*)(xk + 0);
    ulonglong2 a1 = *(const ulonglong2*)(xk + 2);
    ulonglong2 a2 = *(const ulonglong2*)(xk + 4);
    ulonglong2 a3 = *(const ulonglong2*)(xk + 6);
    ulonglong2 a4 = *(const ulonglong2*)(xk + 8);
    asm("fma.rn.f32x2 %0, %1, %2, %0;" : "+l"(acc[0]) : "l"(a0.x), "l"(wp));
    asm("fma.rn.f32x2 %0, %1, %2, %0;" : "+l"(acc[1]) : "l"(a0.y), "l"(wp));
    asm("fma.rn.f32x2 %0, %1, %2, %0;" : "+l"(acc[2]) : "l"(a1.x), "l"(wp));
    asm("fma.rn.f32x2 %0, %1, %2, %0;" : "+l"(acc[3]) : "l"(a1.y), "l"(wp));
    asm("fma.rn.f32x2 %0, %1, %2, %0;" : "+l"(acc[4]) : "l"(a2.x), "l"(wp));
    asm("fma.rn.f32x2 %0, %1, %2, %0;" : "+l"(acc[5]) : "l"(a2.y), "l"(wp));
    asm("fma.rn.f32x2 %0, %1, %2, %0;" : "+l"(acc[6]) : "l"(a3.x), "l"(wp));
    asm("fma.rn.f32x2 %0, %1, %2, %0;" : "+l"(acc[7]) : "l"(a3.y), "l"(wp));
    asm("fma.rn.f32x2 %0, %1, %2, %0;" : "+l"(acc[8]) : "l"(a4.x), "l"(wp));
    asm("fma.rn.f32x2 %0, %1, %2, %0;" : "+l"(acc[9]) : "l"(a4.y), "l"(wp));
}

__device__ void gemm_logits(const float* __restrict__ emb, const float* xs, int bid, int tid) {
    int m = bid * NTHR + tid;
    if (m >= VV) return;
    unsigned long long acc[10];
#pragma unroll
    for (int j = 0; j < 10; j++) acc[j] = 0ull;
    const float4* Wr = (const float4*)(emb + (size_t)m * DD);
    const unsigned long long* xp = (const unsigned long long*)xs;
    float4 w = Wr[0];
#pragma unroll 2
    for (int kq = 0; kq < 192; kq++) {
        float4 wn = Wr[(kq < 191) ? (kq + 1) : kq];   // prefetch next
        const unsigned long long* x0 = xp + (kq * 4) * 10;
        fma10(w.x, x0, acc);
        fma10(w.y, x0 + 10, acc);
        fma10(w.z, x0 + 20, acc);
        fma10(w.w, x0 + 30, acc);
        w = wn;
    }
#pragma unroll
    for (int j = 0; j < 10; j++) {
        float lo, hi;
        asm("mov.b64 {%0, %1}, %2;" : "=f"(lo), "=f"(hi) : "l"(acc[j]));
        g_logits[2 * j][m] = lo;
        g_logits[2 * j + 1][m] = hi;
    }
}

__device__ __forceinline__ void ins5(float v, int id, float* tv, int* ti) {
    if (v > tv[4] || (v == tv[4] && id < ti[4])) {
        int p = 4;
        while (p > 0 && (v > tv[p - 1] || (v == tv[p - 1] && id < ti[p - 1]))) {
            tv[p] = tv[p - 1]; ti[p] = ti[p - 1]; p--;
        }
        tv[p] = v; ti[p] = id;
    }
}

__global__ void __launch_bounds__(NTHR, 1) decode_all(
    const float* __restrict__ emb, const float* __restrict__ pos,
    const float* __restrict__ ln_emb_g, const float* __restrict__ ln_emb_b,
    const float* __restrict__ self_in_w, const float* __restrict__ self_in_b,
    const float* __restrict__ self_out_w, const float* __restrict__ self_out_b,
    const float* __restrict__ cross_in_w, const float* __restrict__ cross_in_b,
    const float* __restrict__ cross_out_w, const float* __restrict__ cross_out_b,
    const float* __restrict__ ff1_w, const float* __restrict__ ff1_b,
    const float* __restrict__ ff2_w, const float* __restrict__ ff2_b,
    const float* __restrict__ ln1_g, const float* __restrict__ ln1_b,
    const float* __restrict__ ln2_g, const float* __restrict__ ln2_b,
    const float* __restrict__ ln3_g, const float* __restrict__ ln3_b,
    const float* __restrict__ dense_w, const float* __restrict__ dense_b,
    const float* __restrict__ context, const int* __restrict__ source_mask,
    float* __restrict__ outbuf)
{
    extern __shared__ float xs[];
    __shared__ float s_red[NWARP];
    const int tid = threadIdx.x, lane = tid & 31, wid = tid >> 5, bid = blockIdx.x;
    const int gw = bid * NWARP + wid;

    if (bid == 0) {
        if (tid < BB * BEAMW * BUFL) {
            int b = tid / (BEAMW * BUFL), r = tid % (BEAMW * BUFL), k = r / BUFL, p = r % BUFL;
            g_buf[b][k][p] = (k == 0 && p == 0) ? TOK_SOS : 0;
        }
        if (tid < NSEQ * BUFL) ((int*)g_anc)[tid] = tid / BUFL;
        if (tid < BB * BEAMW) ((float*)g_scores)[tid] = (tid % BEAMW == 0) ? 0.f : NEGINF;
    }

    // crossKV precompute
    for (int task = bid; task < 2 * 48; task += NBLK) {
        int l = task / 48, mt = task % 48;
        for (int nt = 0; nt < 26; nt++) {
            int base = nt * 20;
            int nr = min(20, BB * SSL - base);
            __syncthreads();
            {
                const float4* s = (const float4*)(context + (size_t)base * DD);
                for (int i = tid; i < nr * 192; i += NTHR) ((float4*)xs)[i] = s[i];
            }
            __syncthreads();
#pragma unroll
            for (int c = 0; c < 2; c++) {
                int m = mt * 32 + wid * 2 + c;
                const float4* Wr = (const float4*)(cross_in_w + (size_t)l * 3 * DD * DD + (size_t)(DD + m) * DD);
                float4 w0 = Wr[lane], w1 = Wr[lane + 32], w2 = Wr[lane + 64];
                float4 w3 = Wr[lane + 96], w4 = Wr[lane + 128], w5 = Wr[lane + 160];
                float bv = cross_in_b[l * 3 * DD + DD + m];
#pragma unroll
                for (int n = 0; n < 20; n++) {
                    float a = wsum(dot24((const float4*)xs + n * 192, lane, w0, w1, w2, w3, w4, w5));
                    if (n < nr && lane == n) g_crossKV[l][base + n][m] = a + bv;
                }
            }
        }
    }
    gsync();

    for (int t = 0; t < TMAXX; t++) {
        for (int l = 0; l < NLL; l++) {
            // P1: embed/ln3 staging + qkv
            if (l == 0) stage_embed_ln(emb, pos, ln_emb_g, ln_emb_b, t, xs, lane, wid, bid);
            else        stage_ln(&g_y[0][0], ln3_g + (l - 1) * DD, ln3_b + (l - 1) * DD, xs, 1, lane, wid, bid);
            gemmA(self_in_w + (size_t)l * 3 * DD * DD, self_in_b + l * 3 * DD,
                  nullptr, nullptr, 3 * DD, 3, xs, gw, lane, l, t);
            gsync();

            // P2: self-attention with ancestor indirection
            if (gw < NSEQ * HH) {
                int n = gw / HH, h = gw % HH;
                const float4* q4 = (const float4*)(g_t1 + n * DD + h * DHH);
                bool actj = (lane <= t);
                int src = actj ? g_anc[n][lane] : 0;
                float dq = 0.f;
                if (actj) {
                    const float4* k4 = (const float4*)(&g_cacheK[l][src][lane][h * DHH]);
#pragma unroll
                    for (int i = 0; i < 16; i++) {
                        float4 a = q4[i], b = k4[i];
                        dq += a.x * b.x + a.y * b.y + a.z * b.z + a.w * b.w;
                    }
                }
                float sc = actj ? dq * 0.125f : -INFINITY;
                float mx = wmax(sc);
                float e = actj ? expf(sc - mx) : 0.f;
                float aw = e / wsum(e);
                float o0 = 0.f, o1 = 0.f;
                for (int j = 0; j <= t; j++) {
                    float aj = __shfl_sync(0xffffffffu, aw, j);
                    int sj = __shfl_sync(0xffffffffu, src, j);
                    const float* Vr = &g_cacheV[l][sj][j][h * DHH];
                    o0 += aj * Vr[lane]; o1 += aj * Vr[lane + 32];
                }
                g_attn[n][h * DHH + lane] = o0;
                g_attn[n][h * DHH + lane + 32] = o1;
            }
            gsync();

            // P3: self_out + resid
            stage_plain(&g_attn[0][0], xs);
            gemmA(self_out_w + (size_t)l * DD * DD, self_out_b + l * DD,
                  &g_x[0][0], &g_y[0][0], DD, 0, xs, gw, lane, 0, 0);
            gsync();

            // P4: ln1 + cross q
            stage_ln(&g_y[0][0], ln1_g + l * DD, ln1_b + l * DD, xs, 1, lane, wid, bid);
            gemmA(cross_in_w + (size_t)l * 3 * DD * DD, cross_in_b + l * 3 * DD,
                  nullptr, g_t1, DD, 0, xs, gw, lane, 0, 0);
            gsync();

            // P5: cross-attention
            if (gw < NSEQ * HH) {
                int n = gw / HH, h = gw % HH, b = n / BEAMW;
                const float4* q4 = (const float4*)(g_t1 + n * DD + h * DHH);
                float sc[4];
#pragma unroll
                for (int jj = 0; jj < 4; jj++) {
                    int j = lane + 32 * jj;
                    const float4* k4 = (const float4*)(&g_crossKV[l][b * SSL + j][h * DHH]);
                    float d = 0.f;
#pragma unroll
                    for (int i = 0; i < 16; i++) {
                        float4 a = q4[i], bb4 = k4[i];
                        d += a.x * bb4.x + a.y * bb4.y + a.z * bb4.z + a.w * bb4.w;
                    }
                    sc[jj] = (source_mask[b * SSL + j] == 0) ? -1e9f : d * 0.125f;
                }
                float mx = wmax(fmaxf(fmaxf(sc[0], sc[1]), fmaxf(sc[2], sc[3])));
                float e0 = expf(sc[0] - mx), e1 = expf(sc[1] - mx);
                float e2 = expf(sc[2] - mx), e3 = expf(sc[3] - mx);
                float inv = 1.f / wsum(e0 + e1 + e2 + e3);
                float* as = xs + wid * SSL;
                as[lane] = e0 * inv; as[lane + 32] = e1 * inv;
                as[lane + 64] = e2 * inv; as[lane + 96] = e3 * inv;
                __syncwarp();
                float o0 = 0.f, o1 = 0.f;
                for (int j = 0; j < SSL; j++) {
                    float aj = as[j];
                    const float* Vr = &g_crossKV[l][b * SSL + j][DD + h * DHH];
                    o0 += aj * Vr[lane]; o1 += aj * Vr[lane + 32];
                }
                g_attn[n][h * DHH + lane] = o0;
                g_attn[n][h * DHH + lane + 32] = o1;
            }
            gsync();

            // P6: cross_out + resid
            stage_plain(&g_attn[0][0], xs);
            gemmA(cross_out_w + (size_t)l * DD * DD, cross_out_b + l * DD,
                  &g_x[0][0], &g_y[0][0], DD, 0, xs, gw, lane, 0, 0);
            gsync();

            // P7: ln2 + ff1
            stage_ln(&g_y[0][0], ln2_g + l * DD, ln2_b + l * DD, xs, 1, lane, wid, bid);
            gemmA(ff1_w + (size_t)l * DFFL * DD, ff1_b + l * DFFL,
                  nullptr, g_t1, DFFL, 1, xs, gw, lane, 0, 0);
            gsync();

            // P8: ff2 + resid
            gemm_ff2(ff2_w + (size_t)l * DD * DFFL, ff2_b + l * DD,
                     &g_x[0][0], &g_y[0][0], xs, gw, lane, tid);
            gsync();
        }

        // dense (tanh)
        stage_ln(&g_y[0][0], ln3_g + (NLL - 1) * DD, ln3_b + (NLL - 1) * DD, xs, 0, lane, wid, bid);
        gemmA(dense_w, dense_b, nullptr, &g_attn[0][0], DD, 2, xs, gw, lane, 0, 0);
        gsync();

        // logits
        stage_pairs(&g_attn[0][0], xs);
        gemm_logits(emb, xs, bid, tid);
        gsync();

        // fused phase: per-row raw top-5 (blocks 0..119) || lse (blocks 120..139)
        if (bid < 120) {
            int n = bid / 6, sub = bid - (bid / 6) * 6;
            int b2 = n / BEAMW, j = n - b2 * BEAMW;
            float* mv = xs;
            int* mi = (int*)(xs + NTHR * 5);
            float tv[5]; int ti[5];
#pragma unroll
            for (int q = 0; q < 5; q++) { tv[q] = -INFINITY; ti[q] = 0x7fffffff; }
            if (g_buf[b2][j][t] != TOK_EOS) {
                const float* row = &g_logits[n][0];
                const int SLI2 = (VV + 5) / 6;
                int i0 = sub * SLI2, i1 = min(VV, i0 + SLI2);
                for (int v = i0 + tid; v < i1; v += NTHR) ins5(row[v], v, tv, ti);
            }
#pragma unroll
            for (int q = 0; q < 5; q++) { mv[tid * 5 + q] = tv[q]; mi[tid * 5 + q] = ti[q]; }
            __syncthreads();
            for (int stride = NTHR / 2; stride >= 1; stride >>= 1) {
                if (tid < stride) {
                    float av[5], bv[5]; int ai[5], bi[5];
#pragma unroll
                    for (int q = 0; q < 5; q++) {
                        av[q] = mv[tid * 5 + q]; ai[q] = mi[tid * 5 + q];
                        bv[q] = mv[(tid + stride) * 5 + q]; bi[q] = mi[(tid + stride) * 5 + q];
                    }
                    int ia = 0, ib = 0;
#pragma unroll
                    for (int q = 0; q < 5; q++) {
                        bool ta = (av[ia] > bv[ib]) || (av[ia] == bv[ib] && ai[ia] < bi[ib]);
                        float rv = ta ? av[ia] : bv[ib];
                        int ri = ta ? ai[ia] : bi[ib];
                        if (ta) ia++; else ib++;
                        mv[tid * 5 + q] = rv; mi[tid * 5 + q] = ri;
                    }
                }
                __syncthreads();
            }
            if (tid < 5) { g_pv[bid * 5 + tid] = mv[tid]; g_pi[bid * 5 + tid] = mi[tid]; }
        } else if (bid < 140) {
            int n = bid - 120;
            const float* row = &g_logits[n][0];
            float m = -INFINITY;
            for (int i = tid; i < VV; i += NTHR) m = fmaxf(m, row[i]);
            m = wmax(m);
            if (lane == 0) s_red[wid] = m;
            __syncthreads();
            if (wid == 0) {
                float r = (lane < NWARP) ? s_red[lane] : -INFINITY;
                r = wmax(r);
                if (lane == 0) s_red[0] = r;
            }
            __syncthreads();
            float mx = s_red[0];
            __syncthreads();
            float s = 0.f;
            for (int i = tid; i < VV; i += NTHR) s += expf(row[i] - mx);
            s = wsum(s);
            if (lane == 0) s_red[wid] = s;
            __syncthreads();
            if (wid == 0) {
                float r = (lane < NWARP) ? s_red[lane] : 0.f;
                r = wsum(r);
                if (lane == 0) { g_mx[n] = mx; g_lse[n] = logf(r); }
            }
        }
        gsync();

        // merge + beam update + ancestor update
        if (bid < BB && wid == 0) {
            int b = bid;
            float tv[5]; int ti[5];
#pragma unroll
            for (int q = 0; q < 5; q++) { tv[q] = -INFINITY; ti[q] = 0x7fffffff; }
            for (int e = lane; e < 150; e += 32) {
                int j = e / 30, c = e - (e / 30) * 30;
                int n = b * BEAMW + j;
                if (g_buf[b][j][t] == TOK_EOS) {
                    if (c < 5) ins5(NEGINF, j * VV + c, tv, ti);
                } else {
                    int slot = (n * 6 + c / 5) * 5 + (c % 5);
                    float raw = g_pv[slot]; int v = g_pi[slot];
                    float val = (raw - (g_mx[n] + g_lse[n])) + g_scores[b][j];
                    ins5(val, j * VV + v, tv, ti);
                }
            }
#pragma unroll
            for (int off = 16; off; off >>= 1) {
                float ov[5]; int oi[5];
#pragma unroll
                for (int q = 0; q < 5; q++) {
                    ov[q] = __shfl_xor_sync(0xffffffffu, tv[q], off);
                    oi[q] = __shfl_xor_sync(0xffffffffu, ti[q], off);
                }
                int ia = 0, ib = 0;
                float rv[5]; int ri[5];
#pragma unroll
                for (int q = 0; q < 5; q++) {
                    bool ta = (tv[ia] > ov[ib]) || (tv[ia] == ov[ib] && ti[ia] < oi[ib]);
                    rv[q] = ta ? tv[ia] : ov[ib];
                    ri[q] = ta ? ti[ia] : oi[ib];
                    if (ta) ia++; else ib++;
                }
#pragma unroll
                for (int q = 0; q < 5; q++) { tv[q] = rv[q]; ti[q] = ri[q]; }
            }
            int snap[5], sanc[5];
#pragma unroll
            for (int j = 0; j < 5; j++) {
                snap[j] = (lane < BUFL) ? g_buf[b][j][lane] : 0;
                sanc[j] = (lane < BUFL) ? g_anc[b * BEAMW + j][lane] : 0;
            }
            __syncwarp();
#pragma unroll
            for (int k = 0; k < 5; k++) {
                int id = ti[k], pk = id / VV, tok = id - pk * VV;
                if (lane < BUFL) {
                    g_buf[b][k][lane] = (lane == t + 1) ? tok : snap[pk];
                    g_anc[b * BEAMW + k][lane] = (lane <= t) ? sanc[pk] : (b * BEAMW + k);
                }
                if (lane == 0) g_scores[b][k] = tv[k];
            }
        }
        gsync();
    }

    if (bid == 0 && tid < BB * BEAMW) {
        int b = tid / BEAMW, k = tid % BEAMW;
        outbuf[tid] = g_scores[b][k];
        int cum = 0;
        for (int i = 1; i <= TMAXX; i++) {
            int tok = g_buf[b][k][i];
            if (tok == TOK_EOS) cum++;
            outbuf[BB * BEAMW + tid * TMAXX + (i - 1)] = (cum == 0) ? (float)tok : 0.f;
        }
    }
}

extern "C" void kernel_launch(void* const* d_in, const int* in_sizes, int n_in,
                              void* d_out, int out_size) {
    (void)in_sizes; (void)n_in; (void)out_size;
    cudaFuncSetAttribute(decode_all, cudaFuncAttributeMaxDynamicSharedMemorySize, NSEQ * DD * 4);
    decode_all<<<NBLK, NTHR, NSEQ * DD * 4>>>(
        (const float*)d_in[0], (const float*)d_in[1], (const float*)d_in[2], (const float*)d_in[3],
        (const float*)d_in[4], (const float*)d_in[5], (const float*)d_in[6], (const float*)d_in[7],
        (const float*)d_in[8], (const float*)d_in[9], (const float*)d_in[10], (const float*)d_in[11],
        (const float*)d_in[12], (const float*)d_in[13], (const float*)d_in[14], (const float*)d_in[15],
        (const float*)d_in[16], (const float*)d_in[17], (const float*)d_in[18], (const float*)d_in[19],
        (const float*)d_in[20], (const float*)d_in[21], (const float*)d_in[22], (const float*)d_in[23],
        (const float*)d_in[24], (const int*)d_in[25], (float*)d_out);
}